// round 4
// baseline (speedup 1.0000x reference)
#include <cuda_runtime.h>
#include <math.h>

#define LSEQ 45000
#define NTOK 512

// ---------------- device scratch (no allocs allowed) ----------------
__device__ float d_pos[8388608];            // [2][512][512][16]  15 base feats + sign  (33.5MB)
__device__ int   d_topk[2][2][256];
__device__ int   d_idxg[2][512];
__device__ float d_emb[2*512*32];
__device__ float d_kk [2*4*512*32];
__device__ float d_vv [2*4*512*32];
__device__ float d_qcb[2*4*512*32];         // q*scale + rcb
__device__ float d_qrl[2*512*4*32];         // [b][i][h][30 used]
__device__ float d_att[2*512*128];          // attention output pre-Wo
__device__ float d_cc[24];                  // 0..4 c1, 5..9 lz, 10..14 rate, 15..19 conc-1, 20 inv_pmax

// ---------------- setup: basis constants + global gamma max ----------------
__global__ void __launch_bounds__(1024) setup_kernel() {
    __shared__ float red[1024];
    double L2S = log(45000.0) / log(2.0);
    float c1[5], lz[5], rate[5], cm1[5];
    for (int k = 0; k < 5; k++) {
        double lin = 3.0 + (L2S - 3.0) * ((double)k / 4.0);
        float hl = (float)exp2(lin);
        c1[k] = -0.69314718055994531f / hl;
        double mean = 9000.0 * (k + 1);
        double sd = 4500.0;
        float conc = (float)((mean / sd) * (mean / sd));
        float rt = (float)(mean / (sd * sd));
        rate[k] = rt; cm1[k] = conc - 1.0f;
        lz[k] = lgammaf(conc) - conc * logf(rt);
    }
    float m = 1e-8f;
    for (int a_ = threadIdx.x; a_ < LSEQ; a_ += 1024) {
        if (a_ == 0) continue;
        float a = (float)a_;
        float la = logf(a);
        for (int k = 0; k < 5; k++) {
            float p = expf(cm1[k] * la - rate[k] * a - lz[k]) + 1e-8f;
            m = fmaxf(m, p);
        }
    }
    red[threadIdx.x] = m; __syncthreads();
    for (int s = 512; s > 0; s >>= 1) {
        if (threadIdx.x < s) red[threadIdx.x] = fmaxf(red[threadIdx.x], red[threadIdx.x + s]);
        __syncthreads();
    }
    if (threadIdx.x == 0) {
        for (int k = 0; k < 5; k++) { d_cc[k] = c1[k]; d_cc[5+k] = lz[k]; d_cc[10+k] = rate[k]; d_cc[15+k] = cm1[k]; }
        d_cc[20] = 1.0f / red[0];
    }
}

// ---------------- exact top-256 via 64-bit radix select ----------------
__device__ __forceinline__ unsigned long long mkey(float v, int j) {
    unsigned int u = __float_as_uint(v);
    u = (u & 0x80000000u) ? ~u : (u | 0x80000000u);
    return (((unsigned long long)u) << 32) | (unsigned int)(0xFFFFFFFFu - (unsigned int)j);
}

__global__ void __launch_bounds__(256) topk_kernel(const float* __restrict__ att) {
    int b = blockIdx.x >> 1, ch = (blockIdx.x & 1) + 1;
    const float* vals = att + (size_t)(b * 3 + ch) * LSEQ;
    __shared__ unsigned int hist[256];
    __shared__ unsigned long long pref;
    __shared__ int rem, cnt;
    if (threadIdx.x == 0) { pref = 0ull; rem = 256; cnt = 0; }
    __syncthreads();
    for (int shift = 56; shift >= 0; shift -= 8) {
        hist[threadIdx.x] = 0u;
        __syncthreads();
        unsigned long long p = pref;
        unsigned long long mh = (shift == 56) ? 0ull : (~((1ull << (shift + 8)) - 1ull));
        for (int j = threadIdx.x; j < LSEQ; j += 256) {
            unsigned long long k = mkey(vals[j], j);
            if ((k & mh) == p) atomicAdd(&hist[(unsigned int)(k >> shift) & 255u], 1u);
        }
        __syncthreads();
        if (threadIdx.x == 0) {
            int r = rem; unsigned int cum = 0; int sel = 0;
            for (int bin = 255; bin >= 0; bin--) {
                cum += hist[bin];
                if ((int)cum >= r) { sel = bin; rem = r - (int)(cum - hist[bin]); break; }
            }
            pref = p | ((unsigned long long)sel << shift);
        }
        __syncthreads();
    }
    unsigned long long kth = pref;
    for (int j = threadIdx.x; j < LSEQ; j += 256) {
        if (mkey(vals[j], j) >= kth) {
            int pi = atomicAdd(&cnt, 1);
            if (pi < 256) d_topk[b][ch - 1][pi] = j;
        }
    }
}

// ---------------- merge+sort 512 indices, gather embeddings ----------------
__global__ void __launch_bounds__(256) sortgather_kernel(const float* __restrict__ x_skip) {
    int b = blockIdx.x, t = threadIdx.x;
    __shared__ int s[512];
    s[t] = d_topk[b][0][t];
    s[256 + t] = d_topk[b][1][t];
    __syncthreads();
    for (int k = 2; k <= 512; k <<= 1) {
        for (int j = k >> 1; j > 0; j >>= 1) {
            #pragma unroll
            for (int half = 0; half < 2; half++) {
                int idx = half * 256 + t;
                int ixj = idx ^ j;
                if (ixj > idx) {
                    int a = s[idx], c = s[ixj];
                    bool up = ((idx & k) == 0);
                    if ((a > c) == up) { s[idx] = c; s[ixj] = a; }
                }
            }
            __syncthreads();
        }
    }
    d_idxg[b][t] = s[t];
    d_idxg[b][256 + t] = s[256 + t];
    __syncthreads();
    for (int q = t; q < 512 * 32; q += 256) {
        int i = q >> 5, c = q & 31;
        d_emb[(b * 512 + i) * 32 + c] = x_skip[((size_t)b * 32 + c) * LSEQ + s[i]];
    }
}

// ---------------- positional basis features (layer-invariant) ----------------
__global__ void __launch_bounds__(256) pos_kernel() {
    unsigned int id = blockIdx.x * 256u + threadIdx.x;   // 2*512*512 threads
    int b = id >> 18;
    unsigned int r = id & 262143u;
    int i = r >> 9, j = r & 511;
    int d = d_idxg[b][i] - d_idxg[b][j];
    float a = fabsf((float)d);
    float sg = (d > 0) ? 1.f : ((d < 0) ? -1.f : 0.f);
    float f[16];
    #pragma unroll
    for (int k = 0; k < 5; k++) f[k] = expf(d_cc[k] * a);
    f[5] = (1.f  > a) ? 1.f : 0.f;
    f[6] = (3.f  > a) ? 1.f : 0.f;
    f[7] = (7.f  > a) ? 1.f : 0.f;
    f[8] = (15.f > a) ? 1.f : 0.f;
    f[9] = (31.f > a) ? 1.f : 0.f;
    float la = logf(a);                 // a==0 -> -inf -> exp -> 0 (matches xlogy path)
    float invp = d_cc[20];
    #pragma unroll
    for (int k = 0; k < 5; k++) {
        float lp = d_cc[15 + k] * la - d_cc[10 + k] * a;
        f[10 + k] = (expf(lp - d_cc[5 + k]) + 1e-8f) * invp;
    }
    f[15] = sg;
    float4* o = (float4*)(d_pos + (size_t)id * 16u);
    o[0] = make_float4(f[0],  f[1],  f[2],  f[3]);
    o[1] = make_float4(f[4],  f[5],  f[6],  f[7]);
    o[2] = make_float4(f[8],  f[9],  f[10], f[11]);
    o[3] = make_float4(f[12], f[13], f[14], f[15]);
}

// ---------------- per-layer: LN1 + QKV + qrel ----------------
__global__ void __launch_bounds__(128) qkv_kernel(
    const float* __restrict__ ln1g, const float* __restrict__ ln1b,
    const float* __restrict__ Wq, const float* __restrict__ Wk, const float* __restrict__ Wv,
    const float* __restrict__ Wrel, const float* __restrict__ rcb, const float* __restrict__ rpb, int l)
{
    int i = blockIdx.x, b = blockIdx.y, t = threadIdx.x;
    __shared__ float h[32], qp[128];
    __shared__ float mu_s, rs_s;
    const float* e = d_emb + (b * 512 + i) * 32;
    if (t < 32) h[t] = e[t];
    __syncthreads();
    if (t == 0) {
        float s = 0.f;
        for (int c = 0; c < 32; c++) s += h[c];
        float mu = s * (1.f / 32.f);
        float v = 0.f;
        for (int c = 0; c < 32; c++) { float dd = h[c] - mu; v += dd * dd; }
        v *= (1.f / 32.f);
        mu_s = mu; rs_s = rsqrtf(v + 1e-5f);
    }
    __syncthreads();
    float hn = 0.f;
    if (t < 32) hn = (h[t] - mu_s) * rs_s * ln1g[l * 32 + t] + ln1b[l * 32 + t];
    __syncthreads();
    if (t < 32) h[t] = hn;
    __syncthreads();
    const float* wq = Wq + l * 32 * 128;
    const float* wk = Wk + l * 32 * 128;
    const float* wv = Wv + l * 32 * 128;
    float q = 0.f, kk = 0.f, vv = 0.f;
    #pragma unroll 8
    for (int c = 0; c < 32; c++) {
        float hc = h[c];
        q  += hc * wq[c * 128 + t];
        kk += hc * wk[c * 128 + t];
        vv += hc * wv[c * 128 + t];
    }
    q *= 0.17677669529663687f;   // 32^-0.5
    int hh = t >> 5, dd = t & 31;
    int base = ((b * 4 + hh) * 512 + i) * 32 + dd;
    d_kk[base] = kk;
    d_vv[base] = vv;
    d_qcb[base] = q + rcb[(l * 4 + hh) * 32 + dd];
    qp[t] = q + rpb[(l * 4 + hh) * 32 + dd];
    __syncthreads();
    if (t < 120) {
        int h2 = t / 30, f = t % 30;
        const float* wr = Wrel + l * 30 * 128 + f * 128 + h2 * 32;
        const float* qq = qp + h2 * 32;
        float s = 0.f;
        #pragma unroll 8
        for (int dd2 = 0; dd2 < 32; dd2++) s += wr[dd2] * qq[dd2];
        d_qrl[((b * 512 + i) * 4 + h2) * 32 + f] = s;
    }
}

// ---------------- per-layer attention: 8 query rows per block, K/V in smem ----------------
__global__ void __launch_bounds__(128) attn_kernel() {
    extern __shared__ float sm[];
    float* Ks  = sm;                 // 512*33
    float* Vs  = sm + 16896;         // 512*33
    float* ws  = sm + 33792;         // 8*512
    float* ob  = sm + 37888;         // 128*32 (also used as 128-wide scalar reduce buf)
    float* qcs = sm + 41984;         // 8*32
    float* qA  = sm + 42240;         // 8*16
    float* qB  = sm + 42368;         // 8*16
    int t = threadIdx.x;
    int i0 = blockIdx.x * 8;
    int h = blockIdx.y;
    int b = blockIdx.z;
    int base = ((b * 4 + h) * 512) * 32;
    for (int q = t; q < 16384; q += 128) {
        int j = q >> 5, d = q & 31;
        Ks[j * 33 + d] = d_kk[base + q];
        Vs[j * 33 + d] = d_vv[base + q];
    }
    for (int q = t; q < 256; q += 128) {
        int r = q >> 5, d = q & 31;
        qcs[q] = d_qcb[base + (i0 + r) * 32 + d];
    }
    for (int q = t; q < 240; q += 128) {
        int r = q / 30, f = q % 30;
        float v = d_qrl[((b * 512 + i0 + r) * 4 + h) * 32 + f];
        if (f < 15) qA[r * 16 + f] = v; else qB[r * 16 + f - 15] = v;
    }
    __syncthreads();

    for (int r = 0; r < 8; r++) {
        const float* posrow = d_pos + ((size_t)(b * 512 + i0 + r)) * 512 * 16;
        #pragma unroll
        for (int ch = 0; ch < 4; ch++) {
            int j = ch * 128 + t;
            float s = 0.f;
            #pragma unroll
            for (int d = 0; d < 32; d++) s += qcs[r * 32 + d] * Ks[j * 33 + d];
            const float4* pp = (const float4*)(posrow + (size_t)j * 16);
            float4 p0 = pp[0], p1 = pp[1], p2 = pp[2], p3 = pp[3];
            float bf[15] = {p0.x,p0.y,p0.z,p0.w, p1.x,p1.y,p1.z,p1.w, p2.x,p2.y,p2.z,p2.w, p3.x,p3.y,p3.z};
            float sg = p3.w;
            float rel = 0.f;
            #pragma unroll
            for (int f = 0; f < 15; f++) rel += bf[f] * (qA[r * 16 + f] + sg * qB[r * 16 + f]);
            ws[r * 512 + j] = s + rel;
        }
    }
    __syncthreads();

    for (int r = 0; r < 8; r++) {
        float m = -3.0e38f;
        #pragma unroll
        for (int ch = 0; ch < 4; ch++) m = fmaxf(m, ws[r * 512 + ch * 128 + t]);
        ob[t] = m; __syncthreads();
        for (int s = 64; s > 0; s >>= 1) { if (t < s) ob[t] = fmaxf(ob[t], ob[t + s]); __syncthreads(); }
        float mx = ob[0]; __syncthreads();
        float pr[4]; float sl = 0.f;
        #pragma unroll
        for (int ch = 0; ch < 4; ch++) { float e = expf(ws[r * 512 + ch * 128 + t] - mx); pr[ch] = e; sl += e; }
        ob[t] = sl; __syncthreads();
        for (int s = 64; s > 0; s >>= 1) { if (t < s) ob[t] += ob[t + s]; __syncthreads(); }
        float inv = 1.f / ob[0]; __syncthreads();
        float acc[32];
        #pragma unroll
        for (int d = 0; d < 32; d++) acc[d] = 0.f;
        #pragma unroll
        for (int ch = 0; ch < 4; ch++) {
            int j = ch * 128 + t;
            float p = pr[ch] * inv;
            #pragma unroll
            for (int d = 0; d < 32; d++) acc[d] += p * Vs[j * 33 + d];
        }
        #pragma unroll
        for (int d = 0; d < 32; d++) ob[t * 32 + d] = acc[d];
        __syncthreads();
        if (t < 32) {
            float s2 = 0.f;
            for (int u = 0; u < 128; u++) s2 += ob[u * 32 + t];
            d_att[(b * 512 + i0 + r) * 128 + h * 32 + t] = s2;
        }
        __syncthreads();
    }
}

// ---------------- per-layer: Wo proj + residual + LN2 + MLP + residual ----------------
__global__ void __launch_bounds__(128) mlp_kernel(
    const float* __restrict__ Wo, const float* __restrict__ bo,
    const float* __restrict__ ln2g, const float* __restrict__ ln2b,
    const float* __restrict__ W1, const float* __restrict__ b1,
    const float* __restrict__ W2, const float* __restrict__ b2, int l)
{
    int i = blockIdx.x, b = blockIdx.y, t = threadIdx.x;
    __shared__ float o128[128], e32[32], h2[32], tb[512];
    __shared__ float mu_s, rs_s;
    o128[t] = d_att[(b * 512 + i) * 128 + t];
    __syncthreads();
    if (t < 32) {
        const float* wo = Wo + l * 128 * 32;
        float acc = 0.f;
        for (int m = 0; m < 128; m++) acc += o128[m] * wo[m * 32 + t];
        e32[t] = d_emb[(b * 512 + i) * 32 + t] + acc + bo[l * 32 + t];
    }
    __syncthreads();
    if (t == 0) {
        float s = 0.f;
        for (int c = 0; c < 32; c++) s += e32[c];
        float mu = s * (1.f / 32.f);
        float v = 0.f;
        for (int c = 0; c < 32; c++) { float dd = e32[c] - mu; v += dd * dd; }
        v *= (1.f / 32.f);
        mu_s = mu; rs_s = rsqrtf(v + 1e-5f);
    }
    __syncthreads();
    if (t < 32) h2[t] = (e32[t] - mu_s) * rs_s * ln2g[l * 32 + t] + ln2b[l * 32 + t];
    __syncthreads();
    const float* w1 = W1 + l * 32 * 512;
    #pragma unroll
    for (int q = 0; q < 4; q++) {
        int m = q * 128 + t;
        float s = b1[l * 512 + m];
        for (int c = 0; c < 32; c++) s += h2[c] * w1[c * 512 + m];
        tb[m] = 0.5f * s * (1.f + erff(s * 0.70710678118654752f));
    }
    __syncthreads();
    if (t < 32) {
        const float* w2 = W2 + l * 512 * 32;
        float s = 0.f;
        for (int m = 0; m < 512; m++) s += tb[m] * w2[m * 32 + t];
        d_emb[(b * 512 + i) * 32 + t] = e32[t] + s + b2[l * 32 + t];
    }
}

// ---------------- scatter back into [B,C,L] ----------------
__global__ void scatter_kernel(float* __restrict__ out) {
    int i = blockIdx.x, b = blockIdx.y, c = threadIdx.x;
    out[((size_t)b * 32 + c) * LSEQ + d_idxg[b][i]] = d_emb[(b * 512 + i) * 32 + c];
}

// ---------------- launch ----------------
extern "C" void kernel_launch(void* const* d_in, const int* in_sizes, int n_in,
                              void* d_out, int out_size) {
    (void)in_sizes; (void)n_in;
    const float* x_skip    = (const float*)d_in[0];
    const float* attention = (const float*)d_in[1];
    const float* ln1g = (const float*)d_in[2];
    const float* ln1b = (const float*)d_in[3];
    const float* Wq   = (const float*)d_in[4];
    const float* Wk   = (const float*)d_in[5];
    const float* Wv   = (const float*)d_in[6];
    const float* Wrel = (const float*)d_in[7];
    const float* rcb  = (const float*)d_in[8];
    const float* rpb  = (const float*)d_in[9];
    const float* Wo   = (const float*)d_in[10];
    const float* bo   = (const float*)d_in[11];
    const float* ln2g = (const float*)d_in[12];
    const float* ln2b = (const float*)d_in[13];
    const float* W1   = (const float*)d_in[14];
    const float* b1   = (const float*)d_in[15];
    const float* W2   = (const float*)d_in[16];
    const float* b2   = (const float*)d_in[17];
    float* out = (float*)d_out;

    const int ATT_SMEM = 42496 * 4;   // 169,984 B
    cudaFuncSetAttribute(attn_kernel, cudaFuncAttributeMaxDynamicSharedMemorySize, ATT_SMEM);

    setup_kernel<<<1, 1024>>>();
    topk_kernel<<<4, 256>>>(attention);
    sortgather_kernel<<<2, 256>>>(x_skip);
    pos_kernel<<<2048, 256>>>();

    for (int l = 0; l < 4; l++) {
        qkv_kernel<<<dim3(512, 2), 128>>>(ln1g, ln1b, Wq, Wk, Wv, Wrel, rcb, rpb, l);
        attn_kernel<<<dim3(64, 4, 2), 128, ATT_SMEM>>>();
        mlp_kernel<<<dim3(512, 2), 128>>>(Wo, bo, ln2g, ln2b, W1, b1, W2, b2, l);
    }

    cudaMemsetAsync(d_out, 0, (size_t)out_size * sizeof(float), 0);
    scatter_kernel<<<dim3(512, 2), 32>>>(out);
}

// round 5
// speedup vs baseline: 1.6618x; 1.6618x over previous
#include <cuda_runtime.h>
#include <cuda_fp16.h>
#include <math.h>

#define LSEQ 45000

// ---------------- device scratch (no allocs allowed) ----------------
__device__ uint4 d_posh4[1048576];          // [2][512][512] * 32B  (16 halfs: 15 feats + sign)
__device__ int   d_topk[2][2][256];
__device__ int   d_idxg[2][512];
__device__ float d_emb[2*512*32];
__device__ float d_kk [2*4*512*32];
__device__ float d_vv [2*4*512*32];
__device__ float d_qcb[2*4*512*32];         // q*scale + rcb
__device__ float d_qrl[2*512*4*32];         // [b][i][h][30 used]
__device__ float d_att[2*512*128];          // attention output pre-Wo
__device__ float d_cc[24];                  // 0..4 c1, 5..9 lz, 10..14 rate, 15..19 conc-1, 20 inv_pmax

__device__ __forceinline__ float2 h2f(unsigned u) {
    __half2 h; *reinterpret_cast<unsigned*>(&h) = u;
    return __half22float2(h);
}

// ---------------- setup: basis constants + global gamma max ----------------
__global__ void __launch_bounds__(1024) setup_kernel() {
    __shared__ float red[1024];
    double L2S = log(45000.0) / log(2.0);
    float c1[5], lz[5], rate[5], cm1[5];
    for (int k = 0; k < 5; k++) {
        double lin = 3.0 + (L2S - 3.0) * ((double)k / 4.0);
        float hl = (float)exp2(lin);
        c1[k] = -0.69314718055994531f / hl;
        double mean = 9000.0 * (k + 1);
        double sd = 4500.0;
        float conc = (float)((mean / sd) * (mean / sd));
        float rt = (float)(mean / (sd * sd));
        rate[k] = rt; cm1[k] = conc - 1.0f;
        lz[k] = lgammaf(conc) - conc * logf(rt);
    }
    float m = 1e-8f;
    for (int a_ = threadIdx.x; a_ < LSEQ; a_ += 1024) {
        if (a_ == 0) continue;
        float a = (float)a_;
        float la = logf(a);
        for (int k = 0; k < 5; k++) {
            float p = expf(cm1[k] * la - rate[k] * a - lz[k]) + 1e-8f;
            m = fmaxf(m, p);
        }
    }
    red[threadIdx.x] = m; __syncthreads();
    for (int s = 512; s > 0; s >>= 1) {
        if (threadIdx.x < s) red[threadIdx.x] = fmaxf(red[threadIdx.x], red[threadIdx.x + s]);
        __syncthreads();
    }
    if (threadIdx.x == 0) {
        for (int k = 0; k < 5; k++) { d_cc[k] = c1[k]; d_cc[5+k] = lz[k]; d_cc[10+k] = rate[k]; d_cc[15+k] = cm1[k]; }
        d_cc[20] = 1.0f / red[0];
    }
}

// ---------------- exact top-256 via 64-bit radix select ----------------
__device__ __forceinline__ unsigned long long mkey(float v, int j) {
    unsigned int u = __float_as_uint(v);
    u = (u & 0x80000000u) ? ~u : (u | 0x80000000u);
    return (((unsigned long long)u) << 32) | (unsigned int)(0xFFFFFFFFu - (unsigned int)j);
}

__global__ void __launch_bounds__(256) topk_kernel(const float* __restrict__ att) {
    int b = blockIdx.x >> 1, ch = (blockIdx.x & 1) + 1;
    const float* vals = att + (size_t)(b * 3 + ch) * LSEQ;
    __shared__ unsigned int hist[8][256];
    __shared__ unsigned int comb[256];
    __shared__ unsigned long long pref;
    __shared__ int rem, cnt;
    int t = threadIdx.x, w = t >> 5;
    if (t == 0) { pref = 0ull; rem = 256; cnt = 0; }
    __syncthreads();
    for (int shift = 56; shift >= 0; shift -= 8) {
        #pragma unroll
        for (int ww = 0; ww < 8; ww++) hist[ww][t] = 0u;
        __syncthreads();
        unsigned long long p = pref;
        unsigned long long mh = (shift == 56) ? 0ull : (~((1ull << (shift + 8)) - 1ull));
        for (int j = t; j < LSEQ; j += 256) {
            unsigned long long k = mkey(vals[j], j);
            if ((k & mh) == p) atomicAdd(&hist[w][(unsigned int)(k >> shift) & 255u], 1u);
        }
        __syncthreads();
        unsigned int tot = 0;
        #pragma unroll
        for (int ww = 0; ww < 8; ww++) tot += hist[ww][t];
        comb[t] = tot;
        __syncthreads();
        if (t == 0) {
            int r = rem; unsigned int cum = 0; int sel = 0;
            for (int bin = 255; bin >= 0; bin--) {
                cum += comb[bin];
                if ((int)cum >= r) { sel = bin; rem = r - (int)(cum - comb[bin]); break; }
            }
            pref = p | ((unsigned long long)sel << shift);
        }
        __syncthreads();
    }
    unsigned long long kth = pref;
    for (int j = t; j < LSEQ; j += 256) {
        if (mkey(vals[j], j) >= kth) {
            int pi = atomicAdd(&cnt, 1);
            if (pi < 256) d_topk[b][ch - 1][pi] = j;
        }
    }
}

// ---------------- merge+sort 512 indices, gather embeddings ----------------
__global__ void __launch_bounds__(256) sortgather_kernel(const float* __restrict__ x_skip) {
    int b = blockIdx.x, t = threadIdx.x;
    __shared__ int s[512];
    s[t] = d_topk[b][0][t];
    s[256 + t] = d_topk[b][1][t];
    __syncthreads();
    for (int k = 2; k <= 512; k <<= 1) {
        for (int j = k >> 1; j > 0; j >>= 1) {
            #pragma unroll
            for (int half = 0; half < 2; half++) {
                int idx = half * 256 + t;
                int ixj = idx ^ j;
                if (ixj > idx) {
                    int a = s[idx], c = s[ixj];
                    bool up = ((idx & k) == 0);
                    if ((a > c) == up) { s[idx] = c; s[ixj] = a; }
                }
            }
            __syncthreads();
        }
    }
    d_idxg[b][t] = s[t];
    d_idxg[b][256 + t] = s[256 + t];
    __syncthreads();
    for (int q = t; q < 512 * 32; q += 256) {
        int i = q >> 5, c = q & 31;
        d_emb[(b * 512 + i) * 32 + c] = x_skip[((size_t)b * 32 + c) * LSEQ + s[i]];
    }
}

// ---------------- positional basis features (layer-invariant, fp16 packed) ----------------
__global__ void __launch_bounds__(256) pos_kernel() {
    unsigned int id = blockIdx.x * 256u + threadIdx.x;   // 2*512*512 threads
    int b = id >> 18;
    unsigned int r = id & 262143u;
    int i = r >> 9, j = r & 511;
    int d = d_idxg[b][i] - d_idxg[b][j];
    float a = fabsf((float)d);
    float sg = (d > 0) ? 1.f : ((d < 0) ? -1.f : 0.f);
    float f[16];
    #pragma unroll
    for (int k = 0; k < 5; k++) f[k] = expf(d_cc[k] * a);
    f[5] = (1.f  > a) ? 1.f : 0.f;
    f[6] = (3.f  > a) ? 1.f : 0.f;
    f[7] = (7.f  > a) ? 1.f : 0.f;
    f[8] = (15.f > a) ? 1.f : 0.f;
    f[9] = (31.f > a) ? 1.f : 0.f;
    float la = logf(a);                 // a==0 -> -inf -> exp -> 0 (matches xlogy path)
    float invp = d_cc[20];
    #pragma unroll
    for (int k = 0; k < 5; k++) {
        float lp = d_cc[15 + k] * la - d_cc[10 + k] * a;
        f[10 + k] = (expf(lp - d_cc[5 + k]) + 1e-8f) * invp;
    }
    f[15] = sg;
    unsigned u[8];
    #pragma unroll
    for (int k = 0; k < 8; k++) {
        __half2 hh = __floats2half2_rn(f[2 * k], f[2 * k + 1]);
        u[k] = *reinterpret_cast<unsigned*>(&hh);
    }
    uint4* o = d_posh4 + (size_t)id * 2u;
    o[0] = make_uint4(u[0], u[1], u[2], u[3]);
    o[1] = make_uint4(u[4], u[5], u[6], u[7]);
}

// ---------------- per-layer: LN1 + QKV + qrel (8 tokens/block, weights in smem) ----------------
__global__ void __launch_bounds__(256) qkv_kernel(
    const float* __restrict__ ln1g, const float* __restrict__ ln1b,
    const float* __restrict__ Wq, const float* __restrict__ Wk, const float* __restrict__ Wv,
    const float* __restrict__ Wrel, const float* __restrict__ rcb, const float* __restrict__ rpb, int l)
{
    extern __shared__ float sm[];
    float* Wqs = sm;                  // 4096
    float* Wks = sm + 4096;           // 4096
    float* Wvs = sm + 8192;           // 4096
    float* Wrs = sm + 12288;          // 30*129 = 3870
    float* hs  = sm + 16160;          // 8*32
    float* qp  = sm + 16416;          // 8*128
    int t = threadIdx.x, lane = t & 31, w = t >> 5;
    int i0 = blockIdx.x * 8, b = blockIdx.y;

    for (int q = t; q < 4096; q += 256) {
        Wqs[q] = Wq[l * 4096 + q];
        Wks[q] = Wk[l * 4096 + q];
        Wvs[q] = Wv[l * 4096 + q];
    }
    for (int q = t; q < 3840; q += 256) {
        int f = q >> 7, c = q & 127;
        Wrs[f * 129 + c] = Wrel[l * 3840 + q];
    }
    // LN1: warp per token
    {
        float x = d_emb[(b * 512 + i0 + w) * 32 + lane];
        float s1 = x;
        #pragma unroll
        for (int o = 16; o > 0; o >>= 1) s1 += __shfl_xor_sync(0xffffffffu, s1, o);
        float mu = s1 * (1.f / 32.f);
        float dd = x - mu;
        float s2 = dd * dd;
        #pragma unroll
        for (int o = 16; o > 0; o >>= 1) s2 += __shfl_xor_sync(0xffffffffu, s2, o);
        float rs = rsqrtf(s2 * (1.f / 32.f) + 1e-5f);
        hs[w * 32 + lane] = dd * rs * ln1g[l * 32 + lane] + ln1b[l * 32 + lane];
    }
    __syncthreads();

    int c = t & 127, tg = t >> 7;   // tg in {0,1}: tokens tg*4 .. tg*4+3
    int hh = c >> 5, dd = c & 31;
    float rc = rcb[(l * 4 + hh) * 32 + dd];
    float rp = rpb[(l * 4 + hh) * 32 + dd];
    #pragma unroll
    for (int tk = 0; tk < 4; tk++) {
        int tok = tg * 4 + tk;
        float q = 0.f, kk = 0.f, vv = 0.f;
        #pragma unroll
        for (int cc = 0; cc < 32; cc++) {
            float hc = hs[tok * 32 + cc];
            q  += hc * Wqs[cc * 128 + c];
            kk += hc * Wks[cc * 128 + c];
            vv += hc * Wvs[cc * 128 + c];
        }
        q *= 0.17677669529663687f;
        int base = ((b * 4 + hh) * 512 + (i0 + tok)) * 32 + dd;
        d_kk[base] = kk;
        d_vv[base] = vv;
        d_qcb[base] = q + rc;
        qp[tok * 128 + c] = q + rp;
    }
    __syncthreads();

    // qrel: lane = feature f (0..29), warp = token
    int f = lane, tok = w;
    if (f < 30) {
        #pragma unroll
        for (int h2 = 0; h2 < 4; h2++) {
            float s = 0.f;
            #pragma unroll
            for (int d2 = 0; d2 < 32; d2++)
                s += Wrs[f * 129 + h2 * 32 + d2] * qp[tok * 128 + h2 * 32 + d2];
            d_qrl[((b * 512 + i0 + tok) * 4 + h2) * 32 + f] = s;
        }
    }
}

// ---------------- per-layer attention: warp-per-row, shuffle softmax ----------------
__global__ void __launch_bounds__(256, 1) attn_kernel() {
    extern __shared__ float sm[];
    float* Ks   = sm;                 // 512*33 = 16896
    float* Vs   = sm + 16896;         // 16896
    float* qcs  = sm + 33792;         // 8*32
    float* qAs  = sm + 34048;         // 8*16
    float* qBs  = sm + 34176;         // 8*16
    float* sred = sm + 34304;         // 8 * 32*33 = 8448
    int t = threadIdx.x, lane = t & 31, w = t >> 5;
    int i0 = blockIdx.x * 8;
    int hd = blockIdx.y;
    int b = blockIdx.z;
    int base = ((b * 4 + hd) * 512) * 32;

    for (int q = t; q < 16384; q += 256) {
        int j = q >> 5, d = q & 31;
        Ks[j * 33 + d] = d_kk[base + q];
        Vs[j * 33 + d] = d_vv[base + q];
    }
    {
        int r = t >> 5, d = t & 31;
        qcs[t] = d_qcb[base + (i0 + r) * 32 + d];
    }
    if (t < 240) {
        int r = t / 30, f = t % 30;
        float v = d_qrl[((b * 512 + i0 + r) * 4 + hd) * 32 + f];
        if (f < 15) qAs[r * 16 + f] = v; else qBs[r * 16 + f - 15] = v;
    }
    __syncthreads();

    // warp w owns query row r = w
    float qd[32];
    #pragma unroll
    for (int d = 0; d < 32; d++) qd[d] = qcs[w * 32 + d];
    float qa[15], qb[15];
    #pragma unroll
    for (int f = 0; f < 15; f++) { qa[f] = qAs[w * 16 + f]; qb[f] = qBs[w * 16 + f]; }

    const uint4* prow = d_posh4 + ((size_t)((b * 512 + i0 + w) * 512)) * 2;

    float s[16];
    #pragma unroll
    for (int q = 0; q < 16; q++) {
        int j = (q << 5) | lane;
        float sc = 0.f;
        #pragma unroll
        for (int d = 0; d < 32; d++) sc += qd[d] * Ks[j * 33 + d];
        uint4 A = prow[(size_t)j * 2], B = prow[(size_t)j * 2 + 1];
        float g[16];
        float2 t2;
        t2 = h2f(A.x); g[0] = t2.x; g[1] = t2.y;
        t2 = h2f(A.y); g[2] = t2.x; g[3] = t2.y;
        t2 = h2f(A.z); g[4] = t2.x; g[5] = t2.y;
        t2 = h2f(A.w); g[6] = t2.x; g[7] = t2.y;
        t2 = h2f(B.x); g[8] = t2.x; g[9] = t2.y;
        t2 = h2f(B.y); g[10] = t2.x; g[11] = t2.y;
        t2 = h2f(B.z); g[12] = t2.x; g[13] = t2.y;
        t2 = h2f(B.w); g[14] = t2.x; g[15] = t2.y;
        float dA = 0.f, dB = 0.f;
        #pragma unroll
        for (int f = 0; f < 15; f++) { dA += g[f] * qa[f]; dB += g[f] * qb[f]; }
        s[q] = sc + dA + g[15] * dB;
    }

    // softmax across 512 (16 regs x 32 lanes) via shuffles
    float m = -3.0e38f;
    #pragma unroll
    for (int q = 0; q < 16; q++) m = fmaxf(m, s[q]);
    #pragma unroll
    for (int o = 16; o > 0; o >>= 1) m = fmaxf(m, __shfl_xor_sync(0xffffffffu, m, o));
    float sum = 0.f;
    #pragma unroll
    for (int q = 0; q < 16; q++) { s[q] = expf(s[q] - m); sum += s[q]; }
    #pragma unroll
    for (int o = 16; o > 0; o >>= 1) sum += __shfl_xor_sync(0xffffffffu, sum, o);
    float inv = 1.f / sum;

    // PV: acc[d] = sum_j p[j] * V[j][d]
    float acc[32];
    #pragma unroll
    for (int d = 0; d < 32; d++) acc[d] = 0.f;
    #pragma unroll
    for (int q = 0; q < 16; q++) {
        int j = (q << 5) | lane;
        float p = s[q];
        #pragma unroll
        for (int d = 0; d < 32; d++) acc[d] += p * Vs[j * 33 + d];
    }
    // cross-lane reduce via padded smem transpose
    float* sr = sred + w * (32 * 33);
    #pragma unroll
    for (int d = 0; d < 32; d++) sr[lane * 33 + d] = acc[d];
    __syncwarp();
    float o = 0.f;
    #pragma unroll
    for (int l2 = 0; l2 < 32; l2++) o += sr[l2 * 33 + lane];
    o *= inv;
    d_att[(b * 512 + i0 + w) * 128 + hd * 32 + lane] = o;
}

// ---------------- per-layer: Wo + residual + LN2 + MLP + residual (8 tokens/block) ----------------
__global__ void __launch_bounds__(256, 1) mlp_kernel(
    const float* __restrict__ Wo, const float* __restrict__ bo,
    const float* __restrict__ ln2g, const float* __restrict__ ln2b,
    const float* __restrict__ W1, const float* __restrict__ b1,
    const float* __restrict__ W2, const float* __restrict__ b2, int l)
{
    extern __shared__ float sm[];
    float* Wos = sm;                  // 4096
    float* W1s = sm + 4096;           // 16384
    float* W2s = sm + 20480;          // 16384
    float* ats = sm + 36864;          // 8*128 = 1024
    float* es  = sm + 37888;          // 8*32
    float* h2s = sm + 38144;          // 8*32
    float* tbs = sm + 38400;          // 8*512 = 4096
    int t = threadIdx.x, lane = t & 31, w = t >> 5;
    int i0 = blockIdx.x * 8, b = blockIdx.y;

    for (int q = t; q < 4096; q += 256) Wos[q] = Wo[l * 4096 + q];
    for (int q = t; q < 16384; q += 256) { W1s[q] = W1[l * 16384 + q]; W2s[q] = W2[l * 16384 + q]; }
    for (int q = t; q < 1024; q += 256) ats[q] = d_att[(b * 512 + i0) * 128 + q];
    __syncthreads();

    // Wo projection + residual: thread -> (tok = t>>5, c = t&31)
    {
        int tok = w, c = lane;
        float acc = 0.f;
        #pragma unroll 8
        for (int m = 0; m < 128; m++) acc += ats[tok * 128 + m] * Wos[m * 32 + c];
        es[tok * 32 + c] = d_emb[(b * 512 + i0 + tok) * 32 + c] + acc + bo[l * 32 + c];
    }
    __syncthreads();
    // LN2: warp per token via shuffles
    {
        float x = es[w * 32 + lane];
        float s1 = x;
        #pragma unroll
        for (int o = 16; o > 0; o >>= 1) s1 += __shfl_xor_sync(0xffffffffu, s1, o);
        float mu = s1 * (1.f / 32.f);
        float dd = x - mu;
        float s2 = dd * dd;
        #pragma unroll
        for (int o = 16; o > 0; o >>= 1) s2 += __shfl_xor_sync(0xffffffffu, s2, o);
        float rs = rsqrtf(s2 * (1.f / 32.f) + 1e-5f);
        h2s[w * 32 + lane] = dd * rs * ln2g[l * 32 + lane] + ln2b[l * 32 + lane];
    }
    __syncthreads();
    // W1 + gelu: thread handles m = t and m = t+256, all 8 tokens
    #pragma unroll
    for (int rep = 0; rep < 2; rep++) {
        int m = t + rep * 256;
        float wcol[32];
        #pragma unroll
        for (int cc = 0; cc < 32; cc++) wcol[cc] = W1s[cc * 512 + m];
        float bb = b1[l * 512 + m];
        #pragma unroll
        for (int tok = 0; tok < 8; tok++) {
            float s = bb;
            #pragma unroll
            for (int cc = 0; cc < 32; cc++) s += h2s[tok * 32 + cc] * wcol[cc];
            tbs[tok * 512 + m] = 0.5f * s * (1.f + erff(s * 0.70710678118654752f));
        }
    }
    __syncthreads();
    // W2 + residual: thread -> (tok, c)
    {
        int tok = w, c = lane;
        float s = 0.f;
        #pragma unroll 8
        for (int m = 0; m < 512; m++) s += tbs[tok * 512 + m] * W2s[m * 32 + c];
        d_emb[(b * 512 + i0 + tok) * 32 + c] = es[tok * 32 + c] + s + b2[l * 32 + c];
    }
}

// ---------------- scatter back into [B,C,L] ----------------
__global__ void scatter_kernel(float* __restrict__ out) {
    int i = blockIdx.x, b = blockIdx.y, c = threadIdx.x;
    out[((size_t)b * 32 + c) * LSEQ + d_idxg[b][i]] = d_emb[(b * 512 + i) * 32 + c];
}

// ---------------- launch ----------------
extern "C" void kernel_launch(void* const* d_in, const int* in_sizes, int n_in,
                              void* d_out, int out_size) {
    (void)in_sizes; (void)n_in;
    const float* x_skip    = (const float*)d_in[0];
    const float* attention = (const float*)d_in[1];
    const float* ln1g = (const float*)d_in[2];
    const float* ln1b = (const float*)d_in[3];
    const float* Wq   = (const float*)d_in[4];
    const float* Wk   = (const float*)d_in[5];
    const float* Wv   = (const float*)d_in[6];
    const float* Wrel = (const float*)d_in[7];
    const float* rcb  = (const float*)d_in[8];
    const float* rpb  = (const float*)d_in[9];
    const float* Wo   = (const float*)d_in[10];
    const float* bo   = (const float*)d_in[11];
    const float* ln2g = (const float*)d_in[12];
    const float* ln2b = (const float*)d_in[13];
    const float* W1   = (const float*)d_in[14];
    const float* b1   = (const float*)d_in[15];
    const float* W2   = (const float*)d_in[16];
    const float* b2   = (const float*)d_in[17];
    float* out = (float*)d_out;

    const int ATT_SMEM = 42752 * 4;   // 171,008 B
    const int MLP_SMEM = 42496 * 4;   // 169,984 B
    const int QKV_SMEM = 17440 * 4;   //  69,760 B
    cudaFuncSetAttribute(attn_kernel, cudaFuncAttributeMaxDynamicSharedMemorySize, ATT_SMEM);
    cudaFuncSetAttribute(mlp_kernel,  cudaFuncAttributeMaxDynamicSharedMemorySize, MLP_SMEM);
    cudaFuncSetAttribute(qkv_kernel,  cudaFuncAttributeMaxDynamicSharedMemorySize, QKV_SMEM);

    setup_kernel<<<1, 1024>>>();
    topk_kernel<<<4, 256>>>(attention);
    sortgather_kernel<<<2, 256>>>(x_skip);
    pos_kernel<<<2048, 256>>>();

    for (int l = 0; l < 4; l++) {
        qkv_kernel<<<dim3(64, 2), 256, QKV_SMEM>>>(ln1g, ln1b, Wq, Wk, Wv, Wrel, rcb, rpb, l);
        attn_kernel<<<dim3(64, 4, 2), 256, ATT_SMEM>>>();
        mlp_kernel<<<dim3(64, 2), 256, MLP_SMEM>>>(Wo, bo, ln2g, ln2b, W1, b1, W2, b2, l);
    }

    cudaMemsetAsync(d_out, 0, (size_t)out_size * sizeof(float), 0);
    scatter_kernel<<<dim3(512, 2), 32>>>(out);
}

// round 6
// speedup vs baseline: 2.6479x; 1.5934x over previous
#include <cuda_runtime.h>
#include <cuda_fp16.h>
#include <math.h>

#define LSEQ 45000

// ---------------- device scratch (no allocs allowed) ----------------
__device__ uint4 d_posh4[1048576];          // [2][512][512] * 32B  (16 halfs: 15 feats + sign)
__device__ int   d_topk[2][2][256];
__device__ int   d_idxg[2][512];
__device__ float d_emb[2*512*32];
__device__ float d_kk [2*4*512*32];
__device__ float d_vv [2*4*512*32];
__device__ float d_qcb[2*4*512*32];         // q*scale + rcb
__device__ float d_qrl[2*512*4*32];         // [b][i][h][30 used]
__device__ float d_att[2*512*128];          // attention output pre-Wo
__device__ float d_cc[24];                  // 0..4 c1, 5..9 lz, 10..14 rate, 15..19 conc-1
__device__ int   d_pmaxbits;                // global gamma max (positive-float bits)

__device__ __forceinline__ __half2 u2h(unsigned u) { return *reinterpret_cast<__half2*>(&u); }

// ---------------- setup: basis constants + global gamma max (32 blocks) ----------------
__global__ void __launch_bounds__(1024) setup_kernel() {
    __shared__ float red[1024];
    double L2S = log(45000.0) / log(2.0);
    float c1[5], lz[5], rate[5], cm1[5];
    for (int k = 0; k < 5; k++) {
        double lin = 3.0 + (L2S - 3.0) * ((double)k / 4.0);
        float hl = (float)exp2(lin);
        c1[k] = -0.69314718055994531f / hl;
        double mean = 9000.0 * (k + 1);
        double sd = 4500.0;
        float conc = (float)((mean / sd) * (mean / sd));
        float rt = (float)(mean / (sd * sd));
        rate[k] = rt; cm1[k] = conc - 1.0f;
        lz[k] = lgammaf(conc) - conc * logf(rt);
    }
    float m = 1e-8f;
    for (int a_ = blockIdx.x * 1024 + threadIdx.x; a_ < LSEQ; a_ += 32768) {
        if (a_ == 0) continue;
        float a = (float)a_;
        float la = logf(a);
        for (int k = 0; k < 5; k++) {
            float p = expf(cm1[k] * la - rate[k] * a - lz[k]) + 1e-8f;
            m = fmaxf(m, p);
        }
    }
    red[threadIdx.x] = m; __syncthreads();
    for (int s = 512; s > 0; s >>= 1) {
        if (threadIdx.x < s) red[threadIdx.x] = fmaxf(red[threadIdx.x], red[threadIdx.x + s]);
        __syncthreads();
    }
    if (threadIdx.x == 0) atomicMax(&d_pmaxbits, __float_as_int(red[0]));   // positive floats: int cmp ok
    if (blockIdx.x == 0 && threadIdx.x == 0) {
        for (int k = 0; k < 5; k++) { d_cc[k] = c1[k]; d_cc[5+k] = lz[k]; d_cc[10+k] = rate[k]; d_cc[15+k] = cm1[k]; }
    }
}

// ---------------- exact top-256: 13-bit hist + compact + small radix select ----------------
#define TK_CAP 2816
__global__ void __launch_bounds__(256) topk_kernel(const float* __restrict__ att) {
    extern __shared__ unsigned char tks[];
    unsigned* hist = (unsigned*)tks;                                     // 8192
    unsigned long long* cand = (unsigned long long*)(tks + 32768);       // 2816
    unsigned* ps = (unsigned*)(tks + 32768 + 22528);                     // 256
    __shared__ unsigned thrT;
    __shared__ int cnt, ocnt, rem_s;
    __shared__ unsigned long long pref_s;
    int t = threadIdx.x, lane = t & 31;
    int b = blockIdx.x >> 1, ch = (blockIdx.x & 1) + 1;
    const float* vals = att + (size_t)(b * 3 + ch) * LSEQ;
    for (int i = t; i < 8192; i += 256) hist[i] = 0;
    if (t == 0) { cnt = 0; ocnt = 0; pref_s = 0ull; rem_s = 256; }
    __syncthreads();
    for (int j = t; j < LSEQ; j += 256) {
        unsigned u = __float_as_uint(vals[j]);
        u = (u & 0x80000000u) ? ~u : (u | 0x80000000u);
        atomicAdd(&hist[u >> 19], 1u);
    }
    __syncthreads();
    {   // per-thread chunk sums (descending bins), 32 bins each
        unsigned sum = 0;
        int base = 8191 - t * 32;
        for (int k = 0; k < 32; k++) sum += hist[base - k];
        ps[t] = sum;
    }
    __syncthreads();
    if (t < 32) {
        // lane covers ps[8*lane .. 8*lane+7] (descending order)
        unsigned s = 0;
        #pragma unroll
        for (int k = 0; k < 8; k++) s += ps[lane * 8 + k];
        unsigned pre = s;
        #pragma unroll
        for (int o = 1; o < 32; o <<= 1) { unsigned v = __shfl_up_sync(0xffffffffu, pre, o); if (lane >= o) pre += v; }
        bool hit = (pre >= 256u) && (pre - s) < 256u;
        unsigned mk = __ballot_sync(0xffffffffu, hit);
        if (lane == (__ffs(mk) - 1)) {
            unsigned cum = pre - s;
            int T = 0;
            for (int k = 0; k < 8; k++) {
                int ci = lane * 8 + k;
                if (cum + ps[ci] >= 256u) {
                    int base = 8191 - ci * 32;
                    for (int kk = 0; kk < 32; kk++) { cum += hist[base - kk]; if (cum >= 256u) { T = base - kk; break; } }
                    break;
                }
                cum += ps[ci];
            }
            thrT = (unsigned)T;
        }
    }
    __syncthreads();
    unsigned T = thrT;
    for (int j = t; j < LSEQ; j += 256) {
        unsigned u = __float_as_uint(vals[j]);
        u = (u & 0x80000000u) ? ~u : (u | 0x80000000u);
        if ((u >> 19) >= T) {
            int pi = atomicAdd(&cnt, 1);
            if (pi < TK_CAP) cand[pi] = (((unsigned long long)u) << 32) | (unsigned)(0xFFFFFFFFu - (unsigned)j);
        }
    }
    __syncthreads();
    int n = cnt < TK_CAP ? cnt : TK_CAP;
    // radix select: 8-bit digits over tiny candidate set
    for (int shift = 56; shift >= 0; shift -= 8) {
        if (t < 256) hist[t] = 0;
        __syncthreads();
        unsigned long long p = pref_s;
        unsigned long long mh = (shift == 56) ? 0ull : ~((1ull << (shift + 8)) - 1ull);
        for (int i = t; i < n; i += 256) {
            unsigned long long k = cand[i];
            if ((k & mh) == p) atomicAdd(&hist[(unsigned)(k >> shift) & 255u], 1u);
        }
        __syncthreads();
        if (t < 32) {
            int r = rem_s;
            unsigned s = 0;
            #pragma unroll
            for (int k = 0; k < 8; k++) s += hist[255 - (lane * 8 + k)];
            unsigned pre = s;
            #pragma unroll
            for (int o = 1; o < 32; o <<= 1) { unsigned v = __shfl_up_sync(0xffffffffu, pre, o); if (lane >= o) pre += v; }
            bool hit = ((int)pre >= r) && (int)(pre - s) < r;
            unsigned mk = __ballot_sync(0xffffffffu, hit);
            if (lane == (__ffs(mk) - 1)) {
                unsigned cum = pre - s;
                for (int k = 0; k < 8; k++) {
                    int bin = 255 - (lane * 8 + k);
                    cum += hist[bin];
                    if ((int)cum >= r) { rem_s = r - (int)(cum - hist[bin]); pref_s = p | ((unsigned long long)bin << shift); break; }
                }
            }
        }
        __syncthreads();
    }
    unsigned long long kth = pref_s;
    for (int i = t; i < n; i += 256) {
        if (cand[i] >= kth) {
            int pi = atomicAdd(&ocnt, 1);
            if (pi < 256) d_topk[b][ch - 1][pi] = (int)(0xFFFFFFFFu - (unsigned)(cand[i] & 0xFFFFFFFFull));
        }
    }
}

// ---------------- merge+sort 512 indices, gather embeddings ----------------
__global__ void __launch_bounds__(256) sortgather_kernel(const float* __restrict__ x_skip) {
    int b = blockIdx.x, t = threadIdx.x;
    __shared__ int s[512];
    s[t] = d_topk[b][0][t];
    s[256 + t] = d_topk[b][1][t];
    __syncthreads();
    for (int k = 2; k <= 512; k <<= 1) {
        for (int j = k >> 1; j > 0; j >>= 1) {
            #pragma unroll
            for (int half = 0; half < 2; half++) {
                int idx = half * 256 + t;
                int ixj = idx ^ j;
                if (ixj > idx) {
                    int a = s[idx], c = s[ixj];
                    bool up = ((idx & k) == 0);
                    if ((a > c) == up) { s[idx] = c; s[ixj] = a; }
                }
            }
            __syncthreads();
        }
    }
    d_idxg[b][t] = s[t];
    d_idxg[b][256 + t] = s[256 + t];
    __syncthreads();
    for (int q = t; q < 512 * 32; q += 256) {
        int i = q >> 5, c = q & 31;
        d_emb[(b * 512 + i) * 32 + c] = x_skip[((size_t)b * 32 + c) * LSEQ + s[i]];
    }
}

// ---------------- positional basis features (layer-invariant, fp16 packed) ----------------
__global__ void __launch_bounds__(256) pos_kernel() {
    unsigned int id = blockIdx.x * 256u + threadIdx.x;   // 2*512*512 threads
    int b = id >> 18;
    unsigned int r = id & 262143u;
    int i = r >> 9, j = r & 511;
    int d = d_idxg[b][i] - d_idxg[b][j];
    float a = fabsf((float)d);
    float sg = (d > 0) ? 1.f : ((d < 0) ? -1.f : 0.f);
    float f[16];
    #pragma unroll
    for (int k = 0; k < 5; k++) f[k] = expf(d_cc[k] * a);
    f[5] = (1.f  > a) ? 1.f : 0.f;
    f[6] = (3.f  > a) ? 1.f : 0.f;
    f[7] = (7.f  > a) ? 1.f : 0.f;
    f[8] = (15.f > a) ? 1.f : 0.f;
    f[9] = (31.f > a) ? 1.f : 0.f;
    float la = logf(a);                 // a==0 -> -inf -> exp -> 0 (matches xlogy path)
    float invp = 1.0f / __int_as_float(d_pmaxbits);
    #pragma unroll
    for (int k = 0; k < 5; k++) {
        float lp = d_cc[15 + k] * la - d_cc[10 + k] * a;
        f[10 + k] = (expf(lp - d_cc[5 + k]) + 1e-8f) * invp;
    }
    f[15] = sg;
    unsigned u[8];
    #pragma unroll
    for (int k = 0; k < 8; k++) {
        __half2 hh = __floats2half2_rn(f[2 * k], f[2 * k + 1]);
        u[k] = *reinterpret_cast<unsigned*>(&hh);
    }
    uint4* o = d_posh4 + (size_t)id * 2u;
    o[0] = make_uint4(u[0], u[1], u[2], u[3]);
    o[1] = make_uint4(u[4], u[5], u[6], u[7]);
}

// ---------------- attention: 16 rows/block, 2 rows/warp, half2 rel dots ----------------
__global__ void __launch_bounds__(256, 1) attn_kernel() {
    extern __shared__ float sm[];
    float* Ks   = sm;                           // 16896
    float* Vs   = sm + 16896;                   // 16896
    float* qcs  = sm + 33792;                   // 512
    unsigned* qAh = (unsigned*)(sm + 34304);    // 128 (16 rows x 8 half2)
    unsigned* qBh = (unsigned*)(sm + 34432);    // 128
    float* sred = sm + 34560;                   // 8448
    int t = threadIdx.x, lane = t & 31, w = t >> 5;
    int i0 = blockIdx.x * 16;
    int hd = blockIdx.y;
    int b = blockIdx.z;
    int base = ((b * 4 + hd) * 512) * 32;
    const float4* kk4 = (const float4*)d_kk;
    const float4* vv4 = (const float4*)d_vv;
    int base4 = base >> 2;
    for (int q = t; q < 4096; q += 256) {
        float4 kv = kk4[base4 + q];
        float4 vv = vv4[base4 + q];
        int j = q >> 3, d4 = (q & 7) << 2;
        float* kp = Ks + j * 33 + d4;
        float* vp = Vs + j * 33 + d4;
        kp[0] = kv.x; kp[1] = kv.y; kp[2] = kv.z; kp[3] = kv.w;
        vp[0] = vv.x; vp[1] = vv.y; vp[2] = vv.z; vp[3] = vv.w;
    }
    for (int q = t; q < 512; q += 256)
        qcs[q] = d_qcb[base + (i0 + (q >> 5)) * 32 + (q & 31)];
    if (t < 128) {
        int r = t >> 3, p = t & 7;
        const float* qr = d_qrl + (((b * 512) + i0 + r) * 4 + hd) * 32;
        int f0 = 2 * p, f1 = f0 + 1;
        float a0 = qr[f0],      a1 = (f1 < 15) ? qr[f1] : 0.f;
        float b0 = qr[15 + f0], b1 = (f1 < 15) ? qr[15 + f1] : 0.f;
        __half2 ha = __floats2half2_rn(a0, a1);
        __half2 hb = __floats2half2_rn(b0, b1);
        qAh[r * 8 + p] = *reinterpret_cast<unsigned*>(&ha);
        qBh[r * 8 + p] = *reinterpret_cast<unsigned*>(&hb);
    }
    __syncthreads();

    int r0 = 2 * w, r1 = r0 + 1;
    float s0[16], s1[16];
    #pragma unroll
    for (int q = 0; q < 16; q++) { s0[q] = 0.f; s1[q] = 0.f; }
    // content: d-outer, q-vector via broadcast LDS
    for (int d = 0; d < 32; d++) {
        float qv0 = qcs[r0 * 32 + d], qv1 = qcs[r1 * 32 + d];
        #pragma unroll
        for (int q = 0; q < 16; q++) {
            float kv = Ks[(q * 32 + lane) * 33 + d];
            s0[q] += qv0 * kv; s1[q] += qv1 * kv;
        }
    }
    // rel: half2 dots
    __half2 qa0[8], qb0[8], qa1[8], qb1[8];
    #pragma unroll
    for (int p = 0; p < 8; p++) {
        qa0[p] = u2h(qAh[r0 * 8 + p]); qb0[p] = u2h(qBh[r0 * 8 + p]);
        qa1[p] = u2h(qAh[r1 * 8 + p]); qb1[p] = u2h(qBh[r1 * 8 + p]);
    }
    const uint4* prow0 = d_posh4 + 2 * (size_t)((b * 512 + i0 + r0) * 512);
    const uint4* prow1 = d_posh4 + 2 * (size_t)((b * 512 + i0 + r1) * 512);
    #pragma unroll 4
    for (int q = 0; q < 16; q++) {
        int j = (q << 5) | lane;
        {
            uint4 A = prow0[2 * j], B = prow0[2 * j + 1];
            __half2 sA = __hmul2(u2h(A.x), qa0[0]);
            sA = __hfma2(u2h(A.y), qa0[1], sA); sA = __hfma2(u2h(A.z), qa0[2], sA);
            sA = __hfma2(u2h(A.w), qa0[3], sA); sA = __hfma2(u2h(B.x), qa0[4], sA);
            sA = __hfma2(u2h(B.y), qa0[5], sA); sA = __hfma2(u2h(B.z), qa0[6], sA);
            sA = __hfma2(u2h(B.w), qa0[7], sA);
            __half2 sB = __hmul2(u2h(A.x), qb0[0]);
            sB = __hfma2(u2h(A.y), qb0[1], sB); sB = __hfma2(u2h(A.z), qb0[2], sB);
            sB = __hfma2(u2h(A.w), qb0[3], sB); sB = __hfma2(u2h(B.x), qb0[4], sB);
            sB = __hfma2(u2h(B.y), qb0[5], sB); sB = __hfma2(u2h(B.z), qb0[6], sB);
            sB = __hfma2(u2h(B.w), qb0[7], sB);
            float2 fA = __half22float2(sA), fB = __half22float2(sB);
            float sg = __high2float(u2h(B.w));
            s0[q] += (fA.x + fA.y) + sg * (fB.x + fB.y);
        }
        {
            uint4 A = prow1[2 * j], B = prow1[2 * j + 1];
            __half2 sA = __hmul2(u2h(A.x), qa1[0]);
            sA = __hfma2(u2h(A.y), qa1[1], sA); sA = __hfma2(u2h(A.z), qa1[2], sA);
            sA = __hfma2(u2h(A.w), qa1[3], sA); sA = __hfma2(u2h(B.x), qa1[4], sA);
            sA = __hfma2(u2h(B.y), qa1[5], sA); sA = __hfma2(u2h(B.z), qa1[6], sA);
            sA = __hfma2(u2h(B.w), qa1[7], sA);
            __half2 sB = __hmul2(u2h(A.x), qb1[0]);
            sB = __hfma2(u2h(A.y), qb1[1], sB); sB = __hfma2(u2h(A.z), qb1[2], sB);
            sB = __hfma2(u2h(A.w), qb1[3], sB); sB = __hfma2(u2h(B.x), qb1[4], sB);
            sB = __hfma2(u2h(B.y), qb1[5], sB); sB = __hfma2(u2h(B.z), qb1[6], sB);
            sB = __hfma2(u2h(B.w), qb1[7], sB);
            float2 fA = __half22float2(sA), fB = __half22float2(sB);
            float sg = __high2float(u2h(B.w));
            s1[q] += (fA.x + fA.y) + sg * (fB.x + fB.y);
        }
    }
    // softmax (per row, warp shuffles)
    float m0 = -3.0e38f, m1 = -3.0e38f;
    #pragma unroll
    for (int q = 0; q < 16; q++) { m0 = fmaxf(m0, s0[q]); m1 = fmaxf(m1, s1[q]); }
    #pragma unroll
    for (int o = 16; o > 0; o >>= 1) {
        m0 = fmaxf(m0, __shfl_xor_sync(0xffffffffu, m0, o));
        m1 = fmaxf(m1, __shfl_xor_sync(0xffffffffu, m1, o));
    }
    float su0 = 0.f, su1 = 0.f;
    #pragma unroll
    for (int q = 0; q < 16; q++) {
        s0[q] = expf(s0[q] - m0); su0 += s0[q];
        s1[q] = expf(s1[q] - m1); su1 += s1[q];
    }
    #pragma unroll
    for (int o = 16; o > 0; o >>= 1) {
        su0 += __shfl_xor_sync(0xffffffffu, su0, o);
        su1 += __shfl_xor_sync(0xffffffffu, su1, o);
    }
    float inv0 = 1.f / su0, inv1 = 1.f / su1;
    // PV
    float acc0[32], acc1[32];
    #pragma unroll
    for (int d = 0; d < 32; d++) { acc0[d] = 0.f; acc1[d] = 0.f; }
    #pragma unroll
    for (int q = 0; q < 16; q++) {
        int j = (q << 5) | lane;
        float p0 = s0[q], p1 = s1[q];
        #pragma unroll
        for (int d = 0; d < 32; d++) {
            float v = Vs[j * 33 + d];
            acc0[d] += p0 * v; acc1[d] += p1 * v;
        }
    }
    // cross-lane reduce rows sequentially via padded transpose
    float* sr = sred + w * 1056;
    #pragma unroll
    for (int d = 0; d < 32; d++) sr[lane * 33 + d] = acc0[d];
    __syncwarp();
    float o0 = 0.f;
    #pragma unroll
    for (int l2 = 0; l2 < 32; l2++) o0 += sr[l2 * 33 + lane];
    d_att[(b * 512 + i0 + r0) * 128 + hd * 32 + lane] = o0 * inv0;
    __syncwarp();
    #pragma unroll
    for (int d = 0; d < 32; d++) sr[lane * 33 + d] = acc1[d];
    __syncwarp();
    float o1 = 0.f;
    #pragma unroll
    for (int l2 = 0; l2 < 32; l2++) o1 += sr[l2 * 33 + lane];
    d_att[(b * 512 + i0 + r1) * 128 + hd * 32 + lane] = o1 * inv1;
}

// ---------------- fused: [mlp layer lm] + [qkv layer lq] for 8 tokens/block ----------------
__global__ void __launch_bounds__(256, 1) fused_kernel(
    const float* __restrict__ Wo, const float* __restrict__ bo,
    const float* __restrict__ ln2g, const float* __restrict__ ln2b,
    const float* __restrict__ W1, const float* __restrict__ b1,
    const float* __restrict__ W2, const float* __restrict__ b2,
    const float* __restrict__ ln1g, const float* __restrict__ ln1b,
    const float* __restrict__ Wq, const float* __restrict__ Wk, const float* __restrict__ Wv,
    const float* __restrict__ Wrel, const float* __restrict__ rcb, const float* __restrict__ rpb,
    int lm, int lq, int do_mlp, int do_qkv)
{
    extern __shared__ float sm[];
    float* W   = sm;                  // 36864 (mlp: Wos/W1s/W2s ; qkv: Wqs/Wks/Wvs/Wrs)
    float* ats = sm + 36864;          // 1024
    float* es  = sm + 37888;          // 256
    float* h2s = sm + 38144;          // 256
    float* tbs = sm + 38400;          // 4096
    float* red = sm + 42496;          // 2048
    float* qp  = sm + 44544;          // 1024
    int t = threadIdx.x, lane = t & 31, w = t >> 5;
    int i0 = blockIdx.x * 8, b = blockIdx.y;

    if (do_mlp) {
        float* Wos = W;
        float* W1s = W + 4096;
        float* W2s = W + 20480;
        {
            float4* d;
            const float4* s4;
            d = (float4*)Wos; s4 = (const float4*)(Wo + lm * 4096);
            for (int q = t; q < 1024; q += 256) d[q] = s4[q];
            d = (float4*)W1s; s4 = (const float4*)(W1 + lm * 16384);
            for (int q = t; q < 4096; q += 256) d[q] = s4[q];
            d = (float4*)W2s; s4 = (const float4*)(W2 + lm * 16384);
            for (int q = t; q < 4096; q += 256) d[q] = s4[q];
        }
        for (int q = t; q < 1024; q += 256) ats[q] = d_att[(b * 512 + i0) * 128 + q];
        __syncthreads();
        // Wo + residual
        {
            float acc = 0.f;
            #pragma unroll 8
            for (int m = 0; m < 128; m++) acc += ats[w * 128 + m] * Wos[m * 32 + lane];
            es[w * 32 + lane] = d_emb[(b * 512 + i0 + w) * 32 + lane] + acc + bo[lm * 32 + lane];
        }
        __syncthreads();
        // LN2 (warp per token)
        {
            float x = es[w * 32 + lane];
            float s1 = x;
            #pragma unroll
            for (int o = 16; o > 0; o >>= 1) s1 += __shfl_xor_sync(0xffffffffu, s1, o);
            float mu = s1 * (1.f / 32.f);
            float dd = x - mu;
            float s2 = dd * dd;
            #pragma unroll
            for (int o = 16; o > 0; o >>= 1) s2 += __shfl_xor_sync(0xffffffffu, s2, o);
            float rs = rsqrtf(s2 * (1.f / 32.f) + 1e-5f);
            h2s[w * 32 + lane] = dd * rs * ln2g[lm * 32 + lane] + ln2b[lm * 32 + lane];
        }
        __syncthreads();
        // W1 + gelu
        #pragma unroll
        for (int rep = 0; rep < 2; rep++) {
            int m = t + rep * 256;
            float wcol[32];
            #pragma unroll
            for (int cc = 0; cc < 32; cc++) wcol[cc] = W1s[cc * 512 + m];
            float bb = b1[lm * 512 + m];
            #pragma unroll
            for (int tok = 0; tok < 8; tok++) {
                float s = bb;
                #pragma unroll
                for (int cc = 0; cc < 32; cc++) s += h2s[tok * 32 + cc] * wcol[cc];
                tbs[tok * 512 + m] = 0.5f * s * (1.f + erff(s * 0.70710678118654752f));
            }
        }
        __syncthreads();
        // W2: m-split partials
        {
            int m0 = w * 64;
            float accw[8];
            #pragma unroll
            for (int tok = 0; tok < 8; tok++) accw[tok] = 0.f;
            for (int mm = 0; mm < 64; mm++) {
                float w2v = W2s[(m0 + mm) * 32 + lane];
                #pragma unroll
                for (int tok = 0; tok < 8; tok++) accw[tok] += tbs[tok * 512 + m0 + mm] * w2v;
            }
            #pragma unroll
            for (int tok = 0; tok < 8; tok++) red[(w * 8 + tok) * 32 + lane] = accw[tok];
        }
        __syncthreads();
        // final reduce + residual write (thread (w,lane) owns (tok=w, c=lane))
        {
            float s = 0.f;
            #pragma unroll
            for (int ww = 0; ww < 8; ww++) s += red[(ww * 8 + w) * 32 + lane];
            float ne = es[w * 32 + lane] + s + b2[lm * 32 + lane];
            d_emb[(b * 512 + i0 + w) * 32 + lane] = ne;
            es[w * 32 + lane] = ne;
        }
    } else {
        es[t] = d_emb[(b * 512 + i0) * 32 + t];
    }

    if (!do_qkv) return;

    // load qkv weights (W region free: W2s last read before previous sync)
    float* Wqs = W;
    float* Wks = W + 4096;
    float* Wvs = W + 8192;
    float* Wrs = W + 12288;   // 30*129
    {
        float4* d;
        const float4* s4;
        d = (float4*)Wqs; s4 = (const float4*)(Wq + lq * 4096);
        for (int q = t; q < 1024; q += 256) d[q] = s4[q];
        d = (float4*)Wks; s4 = (const float4*)(Wk + lq * 4096);
        for (int q = t; q < 1024; q += 256) d[q] = s4[q];
        d = (float4*)Wvs; s4 = (const float4*)(Wv + lq * 4096);
        for (int q = t; q < 1024; q += 256) d[q] = s4[q];
        for (int q = t; q < 3840; q += 256) {
            int f = q >> 7, c = q & 127;
            Wrs[f * 129 + c] = Wrel[lq * 3840 + q];
        }
    }
    __syncthreads();
    // LN1 (warp per token) from es
    {
        float x = es[w * 32 + lane];
        float s1 = x;
        #pragma unroll
        for (int o = 16; o > 0; o >>= 1) s1 += __shfl_xor_sync(0xffffffffu, s1, o);
        float mu = s1 * (1.f / 32.f);
        float dd = x - mu;
        float s2 = dd * dd;
        #pragma unroll
        for (int o = 16; o > 0; o >>= 1) s2 += __shfl_xor_sync(0xffffffffu, s2, o);
        float rs = rsqrtf(s2 * (1.f / 32.f) + 1e-5f);
        h2s[w * 32 + lane] = dd * rs * ln1g[lq * 32 + lane] + ln1b[lq * 32 + lane];
    }
    __syncthreads();
    // QKV matmul
    {
        int c = t & 127, tg = t >> 7;
        int hh = c >> 5, dd = c & 31;
        float rc = rcb[(lq * 4 + hh) * 32 + dd];
        float rp = rpb[(lq * 4 + hh) * 32 + dd];
        #pragma unroll
        for (int tk = 0; tk < 4; tk++) {
            int tok = tg * 4 + tk;
            float q = 0.f, kk = 0.f, vv = 0.f;
            #pragma unroll
            for (int cc = 0; cc < 32; cc++) {
                float hc = h2s[tok * 32 + cc];
                q  += hc * Wqs[cc * 128 + c];
                kk += hc * Wks[cc * 128 + c];
                vv += hc * Wvs[cc * 128 + c];
            }
            q *= 0.17677669529663687f;
            int base = ((b * 4 + hh) * 512 + (i0 + tok)) * 32 + dd;
            d_kk[base] = kk;
            d_vv[base] = vv;
            d_qcb[base] = q + rc;
            qp[tok * 128 + c] = q + rp;
        }
    }
    __syncthreads();
    // qrel: lane = feature, warp = token
    if (lane < 30) {
        int f = lane, tok = w;
        #pragma unroll
        for (int h2 = 0; h2 < 4; h2++) {
            float s = 0.f;
            #pragma unroll
            for (int d2 = 0; d2 < 32; d2++)
                s += Wrs[f * 129 + h2 * 32 + d2] * qp[tok * 128 + h2 * 32 + d2];
            d_qrl[((b * 512 + i0 + tok) * 4 + h2) * 32 + f] = s;
        }
    }
}

// ---------------- scatter back into [B,C,L] ----------------
__global__ void scatter_kernel(float* __restrict__ out) {
    int i = blockIdx.x, b = blockIdx.y, c = threadIdx.x;
    out[((size_t)b * 32 + c) * LSEQ + d_idxg[b][i]] = d_emb[(b * 512 + i) * 32 + c];
}

// ---------------- launch ----------------
extern "C" void kernel_launch(void* const* d_in, const int* in_sizes, int n_in,
                              void* d_out, int out_size) {
    (void)in_sizes; (void)n_in;
    const float* x_skip    = (const float*)d_in[0];
    const float* attention = (const float*)d_in[1];
    const float* ln1g = (const float*)d_in[2];
    const float* ln1b = (const float*)d_in[3];
    const float* Wq   = (const float*)d_in[4];
    const float* Wk   = (const float*)d_in[5];
    const float* Wv   = (const float*)d_in[6];
    const float* Wrel = (const float*)d_in[7];
    const float* rcb  = (const float*)d_in[8];
    const float* rpb  = (const float*)d_in[9];
    const float* Wo   = (const float*)d_in[10];
    const float* bo   = (const float*)d_in[11];
    const float* ln2g = (const float*)d_in[12];
    const float* ln2b = (const float*)d_in[13];
    const float* W1   = (const float*)d_in[14];
    const float* b1   = (const float*)d_in[15];
    const float* W2   = (const float*)d_in[16];
    const float* b2   = (const float*)d_in[17];
    float* out = (float*)d_out;

    const int ATT_SMEM   = 43008 * 4;   // 172032 B
    const int FUSED_SMEM = 45568 * 4;   // 182272 B
    const int TOPK_SMEM  = 32768 + 22528 + 1024;  // 56320 B
    cudaFuncSetAttribute(attn_kernel,  cudaFuncAttributeMaxDynamicSharedMemorySize, ATT_SMEM);
    cudaFuncSetAttribute(fused_kernel, cudaFuncAttributeMaxDynamicSharedMemorySize, FUSED_SMEM);
    cudaFuncSetAttribute(topk_kernel,  cudaFuncAttributeMaxDynamicSharedMemorySize, TOPK_SMEM);

    setup_kernel<<<32, 1024>>>();
    topk_kernel<<<4, 256, TOPK_SMEM>>>(attention);
    sortgather_kernel<<<2, 256>>>(x_skip);
    pos_kernel<<<2048, 256>>>();

    // qkv for layer 0
    fused_kernel<<<dim3(64, 2), 256, FUSED_SMEM>>>(
        Wo, bo, ln2g, ln2b, W1, b1, W2, b2,
        ln1g, ln1b, Wq, Wk, Wv, Wrel, rcb, rpb,
        0, 0, /*do_mlp=*/0, /*do_qkv=*/1);

    for (int l = 0; l < 4; l++) {
        attn_kernel<<<dim3(32, 4, 2), 256, ATT_SMEM>>>();
        fused_kernel<<<dim3(64, 2), 256, FUSED_SMEM>>>(
            Wo, bo, ln2g, ln2b, W1, b1, W2, b2,
            ln1g, ln1b, Wq, Wk, Wv, Wrel, rcb, rpb,
            l, l + 1, /*do_mlp=*/1, /*do_qkv=*/(l < 3) ? 1 : 0);
    }

    cudaMemsetAsync(d_out, 0, (size_t)out_size * sizeof(float), 0);
    scatter_kernel<<<dim3(512, 2), 32>>>(out);
}

// round 7
// speedup vs baseline: 3.2407x; 1.2239x over previous
#include <cuda_runtime.h>
#include <cuda_fp16.h>
#include <math.h>

#define LSEQ 45000

// ---------------- device scratch (no allocs allowed) ----------------
__device__ uint4 d_posh4[1048576];          // [2][512][512] * 32B (16 halfs: 15 feats + sign)
__device__ int   d_topk[2][2][256];
__device__ int   d_idxg[2][512];
__device__ float d_emb[2*512*32];
__device__ __align__(16) __half d_kkh[2*4*32*512];   // [b*4+h][d][j] fp16
__device__ __align__(16) __half d_vvh[2*4*32*512];
__device__ float d_qcb[2*4*512*32];         // q*scale + rcb   [bh][i][d]
__device__ float d_qrl[2*512*4*32];         // [b][i][h][30 used]
__device__ float d_att[2*512*128];          // attention output pre-Wo
__device__ float d_cc[24];                  // 0..4 c1, 5..9 lz, 10..14 rate, 15..19 conc-1
__device__ int   d_pmaxbits;                // global gamma max (positive-float bits)

__device__ __forceinline__ __half2 u2h(unsigned u) { return *reinterpret_cast<__half2*>(&u); }
__device__ __forceinline__ unsigned h2u(__half2 h) { return *reinterpret_cast<unsigned*>(&h); }

// ---------------- prologue: blocks 0-3 top-256 select, blocks 4-35 basis setup ----------------
#define TK_CAP 2816
__global__ void __launch_bounds__(1024) prologue_kernel(const float* __restrict__ att) {
    extern __shared__ unsigned char tks[];
    int t = threadIdx.x, lane = t & 31;

    if (blockIdx.x >= 4) {
        // ---- setup: basis constants + global gamma max ----
        float* red = (float*)tks;
        int bid = blockIdx.x - 4;
        double L2S = log(45000.0) / log(2.0);
        float c1[5], lz[5], rate[5], cm1[5];
        for (int k = 0; k < 5; k++) {
            double lin = 3.0 + (L2S - 3.0) * ((double)k / 4.0);
            float hl = (float)exp2(lin);
            c1[k] = -0.69314718055994531f / hl;
            double mean = 9000.0 * (k + 1);
            double sd = 4500.0;
            float conc = (float)((mean / sd) * (mean / sd));
            float rt = (float)(mean / (sd * sd));
            rate[k] = rt; cm1[k] = conc - 1.0f;
            lz[k] = lgammaf(conc) - conc * logf(rt);
        }
        float m = 1e-8f;
        for (int a_ = bid * 1024 + t; a_ < LSEQ; a_ += 32768) {
            if (a_ == 0) continue;
            float a = (float)a_;
            float la = logf(a);
            for (int k = 0; k < 5; k++) {
                float p = expf(cm1[k] * la - rate[k] * a - lz[k]) + 1e-8f;
                m = fmaxf(m, p);
            }
        }
        red[t] = m; __syncthreads();
        for (int s = 512; s > 0; s >>= 1) {
            if (t < s) red[t] = fmaxf(red[t], red[t + s]);
            __syncthreads();
        }
        if (t == 0) atomicMax(&d_pmaxbits, __float_as_int(red[0]));
        if (bid == 0 && t == 0) {
            for (int k = 0; k < 5; k++) { d_cc[k] = c1[k]; d_cc[5+k] = lz[k]; d_cc[10+k] = rate[k]; d_cc[15+k] = cm1[k]; }
        }
        return;
    }

    // ---- topk: exact top-256 via 13-bit hist + compact + radix select ----
    unsigned* hist = (unsigned*)tks;                                     // 8192 u
    unsigned long long* cand = (unsigned long long*)(tks + 32768);       // 2816
    unsigned* ps = (unsigned*)(tks + 32768 + 22528);                     // 256
    __shared__ unsigned thrT;
    __shared__ int cnt, ocnt, rem_s;
    __shared__ unsigned long long pref_s;
    int b = blockIdx.x >> 1, ch = (blockIdx.x & 1) + 1;
    const float* vals = att + (size_t)(b * 3 + ch) * LSEQ;
    for (int i = t; i < 8192; i += 1024) hist[i] = 0;
    if (t == 0) { cnt = 0; ocnt = 0; pref_s = 0ull; rem_s = 256; }
    __syncthreads();
    for (int j = t; j < LSEQ; j += 1024) {
        unsigned u = __float_as_uint(vals[j]);
        u = (u & 0x80000000u) ? ~u : (u | 0x80000000u);
        atomicAdd(&hist[u >> 19], 1u);
    }
    __syncthreads();
    if (t < 256) {
        unsigned sum = 0;
        int base = 8191 - t * 32;
        for (int k = 0; k < 32; k++) sum += hist[base - k];
        ps[t] = sum;
    }
    __syncthreads();
    if (t < 32) {
        unsigned s = 0;
        #pragma unroll
        for (int k = 0; k < 8; k++) s += ps[lane * 8 + k];
        unsigned pre = s;
        #pragma unroll
        for (int o = 1; o < 32; o <<= 1) { unsigned v = __shfl_up_sync(0xffffffffu, pre, o); if (lane >= o) pre += v; }
        bool hit = (pre >= 256u) && (pre - s) < 256u;
        unsigned mk = __ballot_sync(0xffffffffu, hit);
        if (lane == (__ffs(mk) - 1)) {
            unsigned cum = pre - s;
            int T = 0;
            for (int k = 0; k < 8; k++) {
                int ci = lane * 8 + k;
                if (cum + ps[ci] >= 256u) {
                    int base = 8191 - ci * 32;
                    for (int kk = 0; kk < 32; kk++) { cum += hist[base - kk]; if (cum >= 256u) { T = base - kk; break; } }
                    break;
                }
                cum += ps[ci];
            }
            thrT = (unsigned)T;
        }
    }
    __syncthreads();
    unsigned T = thrT;
    for (int j = t; j < LSEQ; j += 1024) {
        unsigned u = __float_as_uint(vals[j]);
        u = (u & 0x80000000u) ? ~u : (u | 0x80000000u);
        if ((u >> 19) >= T) {
            int pi = atomicAdd(&cnt, 1);
            if (pi < TK_CAP) cand[pi] = (((unsigned long long)u) << 32) | (unsigned)(0xFFFFFFFFu - (unsigned)j);
        }
    }
    __syncthreads();
    int n = cnt < TK_CAP ? cnt : TK_CAP;
    for (int shift = 56; shift >= 0; shift -= 8) {
        if (t < 256) hist[t] = 0;
        __syncthreads();
        unsigned long long p = pref_s;
        unsigned long long mh = (shift == 56) ? 0ull : ~((1ull << (shift + 8)) - 1ull);
        for (int i = t; i < n; i += 1024) {
            unsigned long long k = cand[i];
            if ((k & mh) == p) atomicAdd(&hist[(unsigned)(k >> shift) & 255u], 1u);
        }
        __syncthreads();
        if (t < 32) {
            int r = rem_s;
            unsigned s = 0;
            #pragma unroll
            for (int k = 0; k < 8; k++) s += hist[255 - (lane * 8 + k)];
            unsigned pre = s;
            #pragma unroll
            for (int o = 1; o < 32; o <<= 1) { unsigned v = __shfl_up_sync(0xffffffffu, pre, o); if (lane >= o) pre += v; }
            bool hit = ((int)pre >= r) && (int)(pre - s) < r;
            unsigned mk = __ballot_sync(0xffffffffu, hit);
            if (lane == (__ffs(mk) - 1)) {
                unsigned cum = pre - s;
                for (int k = 0; k < 8; k++) {
                    int bin = 255 - (lane * 8 + k);
                    cum += hist[bin];
                    if ((int)cum >= r) { rem_s = r - (int)(cum - hist[bin]); pref_s = p | ((unsigned long long)bin << shift); break; }
                }
            }
        }
        __syncthreads();
    }
    unsigned long long kth = pref_s;
    for (int i = t; i < n; i += 1024) {
        if (cand[i] >= kth) {
            int pi = atomicAdd(&ocnt, 1);
            if (pi < 256) d_topk[b][ch - 1][pi] = (int)(0xFFFFFFFFu - (unsigned)(cand[i] & 0xFFFFFFFFull));
        }
    }
}

// ---------------- merge+sort 512 indices, gather embeddings ----------------
__global__ void __launch_bounds__(256) sortgather_kernel(const float* __restrict__ x_skip) {
    int b = blockIdx.x, t = threadIdx.x;
    __shared__ int s[512];
    s[t] = d_topk[b][0][t];
    s[256 + t] = d_topk[b][1][t];
    __syncthreads();
    for (int k = 2; k <= 512; k <<= 1) {
        for (int j = k >> 1; j > 0; j >>= 1) {
            #pragma unroll
            for (int half = 0; half < 2; half++) {
                int idx = half * 256 + t;
                int ixj = idx ^ j;
                if (ixj > idx) {
                    int a = s[idx], c = s[ixj];
                    bool up = ((idx & k) == 0);
                    if ((a > c) == up) { s[idx] = c; s[ixj] = a; }
                }
            }
            __syncthreads();
        }
    }
    d_idxg[b][t] = s[t];
    d_idxg[b][256 + t] = s[256 + t];
    __syncthreads();
    for (int q = t; q < 512 * 32; q += 256) {
        int i = q >> 5, c = q & 31;
        d_emb[(b * 512 + i) * 32 + c] = x_skip[((size_t)b * 32 + c) * LSEQ + s[i]];
    }
}

// ---------------- positional basis features (layer-invariant, fp16 packed) ----------------
__global__ void __launch_bounds__(256) pos_kernel() {
    unsigned int id = blockIdx.x * 256u + threadIdx.x;   // 2*512*512 threads
    int b = id >> 18;
    unsigned int r = id & 262143u;
    int i = r >> 9, j = r & 511;
    int d = d_idxg[b][i] - d_idxg[b][j];
    float a = fabsf((float)d);
    float sg = (d > 0) ? 1.f : ((d < 0) ? -1.f : 0.f);
    float f[16];
    #pragma unroll
    for (int k = 0; k < 5; k++) f[k] = expf(d_cc[k] * a);
    f[5] = (1.f  > a) ? 1.f : 0.f;
    f[6] = (3.f  > a) ? 1.f : 0.f;
    f[7] = (7.f  > a) ? 1.f : 0.f;
    f[8] = (15.f > a) ? 1.f : 0.f;
    f[9] = (31.f > a) ? 1.f : 0.f;
    float la = logf(a);                 // a==0 -> -inf -> exp -> 0 (matches xlogy path)
    float invp = 1.0f / __int_as_float(d_pmaxbits);
    #pragma unroll
    for (int k = 0; k < 5; k++) {
        float lp = d_cc[15 + k] * la - d_cc[10 + k] * a;
        f[10 + k] = (expf(lp - d_cc[5 + k]) + 1e-8f) * invp;
    }
    f[15] = sg;
    unsigned u[8];
    #pragma unroll
    for (int k = 0; k < 8; k++) u[k] = h2u(__floats2half2_rn(f[2 * k], f[2 * k + 1]));
    uint4* o = d_posh4 + (size_t)id * 2u;
    o[0] = make_uint4(u[0], u[1], u[2], u[3]);
    o[1] = make_uint4(u[4], u[5], u[6], u[7]);
}

// ---------------- attention: 16 rows/block, 2 rows/warp, fp16 K/V [d][j], 2 CTA/SM ----------------
__global__ void __launch_bounds__(256, 2) attn_kernel() {
    extern __shared__ __align__(16) unsigned char smraw[];
    __half* Kh = (__half*)smraw;                       // 32*512 halfs = 32KB
    __half* Vh = (__half*)(smraw + 32768);             // 32KB
    float* qcs = (float*)(smraw + 65536);              // 512 f
    unsigned* qAh = (unsigned*)(smraw + 67584);        // 128 u
    unsigned* qBh = (unsigned*)(smraw + 68096);        // 128 u  -> total 68608
    int t = threadIdx.x, lane = t & 31, w = t >> 5;
    int i0 = blockIdx.x * 16;
    int hd = blockIdx.y;
    int b = blockIdx.z;
    int bh = b * 4 + hd;

    {   // K/V smem copy (layout preserved)
        const uint4* kg = (const uint4*)(d_kkh + bh * 16384);
        const uint4* vg = (const uint4*)(d_vvh + bh * 16384);
        uint4* ks4 = (uint4*)Kh; uint4* vs4 = (uint4*)Vh;
        for (int q = t; q < 2048; q += 256) { ks4[q] = kg[q]; vs4[q] = vg[q]; }
    }
    for (int q = t; q < 512; q += 256)
        qcs[q] = d_qcb[(bh * 512 + i0 + (q >> 5)) * 32 + (q & 31)];
    if (t < 128) {
        int r = t >> 3, p = t & 7;
        const float* qr = d_qrl + (((b * 512) + i0 + r) * 4 + hd) * 32;
        int f0 = 2 * p, f1 = f0 + 1;
        float a0 = qr[f0],      a1 = (f1 < 15) ? qr[f1] : 0.f;
        float b0 = qr[15 + f0], b1 = (f1 < 15) ? qr[15 + f1] : 0.f;
        qAh[r * 8 + p] = h2u(__floats2half2_rn(a0, a1));
        qBh[r * 8 + p] = h2u(__floats2half2_rn(b0, b1));
    }
    __syncthreads();

    int r0 = 2 * w, r1 = r0 + 1;
    float s0[16], s1[16];
    #pragma unroll
    for (int q = 0; q < 16; q++) { s0[q] = 0.f; s1[q] = 0.f; }

    // content: lane owns j = ch*128 + lane*4 + u
    for (int d = 0; d < 32; d++) {
        float qv0 = qcs[r0 * 32 + d], qv1 = qcs[r1 * 32 + d];
        const uint2* kr = (const uint2*)(Kh + d * 512);
        #pragma unroll
        for (int ch = 0; ch < 4; ch++) {
            uint2 kk = kr[ch * 32 + lane];
            float2 fa = __half22float2(u2h(kk.x));
            float2 fb = __half22float2(u2h(kk.y));
            s0[ch*4+0] += qv0 * fa.x; s0[ch*4+1] += qv0 * fa.y;
            s0[ch*4+2] += qv0 * fb.x; s0[ch*4+3] += qv0 * fb.y;
            s1[ch*4+0] += qv1 * fa.x; s1[ch*4+1] += qv1 * fa.y;
            s1[ch*4+2] += qv1 * fb.x; s1[ch*4+3] += qv1 * fb.y;
        }
    }

    // rel: half2 dot over 15 features + sign
    {
        __half2 qa0[8], qb0[8], qa1[8], qb1[8];
        #pragma unroll
        for (int p = 0; p < 8; p++) {
            qa0[p] = u2h(qAh[r0 * 8 + p]); qb0[p] = u2h(qBh[r0 * 8 + p]);
            qa1[p] = u2h(qAh[r1 * 8 + p]); qb1[p] = u2h(qBh[r1 * 8 + p]);
        }
        const uint4* prow0 = d_posh4 + 2 * (size_t)((b * 512 + i0 + r0) * 512);
        const uint4* prow1 = d_posh4 + 2 * (size_t)((b * 512 + i0 + r1) * 512);
        #pragma unroll
        for (int ch = 0; ch < 4; ch++) {
            #pragma unroll
            for (int u = 0; u < 4; u++) {
                int j = ch * 128 + lane * 4 + u;
                {
                    uint4 A = prow0[2 * j], B = prow0[2 * j + 1];
                    __half2 sA = __hmul2(u2h(A.x), qa0[0]);
                    sA = __hfma2(u2h(A.y), qa0[1], sA); sA = __hfma2(u2h(A.z), qa0[2], sA);
                    sA = __hfma2(u2h(A.w), qa0[3], sA); sA = __hfma2(u2h(B.x), qa0[4], sA);
                    sA = __hfma2(u2h(B.y), qa0[5], sA); sA = __hfma2(u2h(B.z), qa0[6], sA);
                    sA = __hfma2(u2h(B.w), qa0[7], sA);
                    __half2 sB = __hmul2(u2h(A.x), qb0[0]);
                    sB = __hfma2(u2h(A.y), qb0[1], sB); sB = __hfma2(u2h(A.z), qb0[2], sB);
                    sB = __hfma2(u2h(A.w), qb0[3], sB); sB = __hfma2(u2h(B.x), qb0[4], sB);
                    sB = __hfma2(u2h(B.y), qb0[5], sB); sB = __hfma2(u2h(B.z), qb0[6], sB);
                    sB = __hfma2(u2h(B.w), qb0[7], sB);
                    float2 fA = __half22float2(sA), fB = __half22float2(sB);
                    float sg = __high2float(u2h(B.w));
                    s0[ch * 4 + u] += (fA.x + fA.y) + sg * (fB.x + fB.y);
                }
                {
                    uint4 A = prow1[2 * j], B = prow1[2 * j + 1];
                    __half2 sA = __hmul2(u2h(A.x), qa1[0]);
                    sA = __hfma2(u2h(A.y), qa1[1], sA); sA = __hfma2(u2h(A.z), qa1[2], sA);
                    sA = __hfma2(u2h(A.w), qa1[3], sA); sA = __hfma2(u2h(B.x), qa1[4], sA);
                    sA = __hfma2(u2h(B.y), qa1[5], sA); sA = __hfma2(u2h(B.z), qa1[6], sA);
                    sA = __hfma2(u2h(B.w), qa1[7], sA);
                    __half2 sB = __hmul2(u2h(A.x), qb1[0]);
                    sB = __hfma2(u2h(A.y), qb1[1], sB); sB = __hfma2(u2h(A.z), qb1[2], sB);
                    sB = __hfma2(u2h(A.w), qb1[3], sB); sB = __hfma2(u2h(B.x), qb1[4], sB);
                    sB = __hfma2(u2h(B.y), qb1[5], sB); sB = __hfma2(u2h(B.z), qb1[6], sB);
                    sB = __hfma2(u2h(B.w), qb1[7], sB);
                    float2 fA = __half22float2(sA), fB = __half22float2(sB);
                    float sg = __high2float(u2h(B.w));
                    s1[ch * 4 + u] += (fA.x + fA.y) + sg * (fB.x + fB.y);
                }
            }
        }
    }

    // softmax (per row, warp shuffles)
    float m0 = -3.0e38f, m1 = -3.0e38f;
    #pragma unroll
    for (int q = 0; q < 16; q++) { m0 = fmaxf(m0, s0[q]); m1 = fmaxf(m1, s1[q]); }
    #pragma unroll
    for (int o = 16; o > 0; o >>= 1) {
        m0 = fmaxf(m0, __shfl_xor_sync(0xffffffffu, m0, o));
        m1 = fmaxf(m1, __shfl_xor_sync(0xffffffffu, m1, o));
    }
    float su0 = 0.f, su1 = 0.f;
    #pragma unroll
    for (int q = 0; q < 16; q++) {
        s0[q] = expf(s0[q] - m0); su0 += s0[q];
        s1[q] = expf(s1[q] - m1); su1 += s1[q];
    }
    #pragma unroll
    for (int o = 16; o > 0; o >>= 1) {
        su0 += __shfl_xor_sync(0xffffffffu, su0, o);
        su1 += __shfl_xor_sync(0xffffffffu, su1, o);
    }
    float inv0 = 1.f / su0, inv1 = 1.f / su1;

    // PV in two d-halves; butterfly transpose-reduce per half
    #pragma unroll
    for (int pass = 0; pass < 2; pass++) {
        float v[32];
        #pragma unroll
        for (int k = 0; k < 16; k++) {
            int d = pass * 16 + k;
            const uint2* vr = (const uint2*)(Vh + d * 512);
            float a0 = 0.f, a1 = 0.f;
            #pragma unroll
            for (int ch = 0; ch < 4; ch++) {
                uint2 vv = vr[ch * 32 + lane];
                float2 fa = __half22float2(u2h(vv.x));
                float2 fb = __half22float2(u2h(vv.y));
                a0 += s0[ch*4+0]*fa.x + s0[ch*4+1]*fa.y + s0[ch*4+2]*fb.x + s0[ch*4+3]*fb.y;
                a1 += s1[ch*4+0]*fa.x + s1[ch*4+1]*fa.y + s1[ch*4+2]*fb.x + s1[ch*4+3]*fb.y;
            }
            v[k] = a0; v[16 + k] = a1;
        }
        #pragma unroll
        for (int m = 16; m >= 1; m >>= 1) {
            #pragma unroll
            for (int k = 0; k < m; k++) {
                float give = (lane & m) ? v[k] : v[k + m];
                float got = __shfl_xor_sync(0xffffffffu, give, m);
                v[k] = (lane & m) ? (v[k + m] + got) : (v[k] + got);
            }
        }
        float outv = v[0] * ((lane < 16) ? inv0 : inv1);
        int row = (lane < 16) ? r0 : r1;
        int dd = (lane & 15) + pass * 16;
        d_att[(b * 512 + i0 + row) * 128 + hd * 32 + dd] = outv;
    }
}

// ---------------- fused: [mlp layer lm] + [qkv layer lq], 8 tokens/block, direct-LDG weights ----------------
__global__ void __launch_bounds__(256, 1) fused_kernel(
    const float* __restrict__ Wo, const float* __restrict__ bo,
    const float* __restrict__ ln2g, const float* __restrict__ ln2b,
    const float* __restrict__ W1, const float* __restrict__ b1,
    const float* __restrict__ W2, const float* __restrict__ b2,
    const float* __restrict__ ln1g, const float* __restrict__ ln1b,
    const float* __restrict__ Wq, const float* __restrict__ Wk, const float* __restrict__ Wv,
    const float* __restrict__ Wrel, const float* __restrict__ rcb, const float* __restrict__ rpb,
    int lm, int lq, int do_mlp, int do_qkv)
{
    extern __shared__ float sm[];
    float* ats = sm;                  // 1024
    float* es  = sm + 1024;           // 256
    float* h2s = sm + 1280;           // 256
    float* tbs = sm + 1536;           // 4096
    float* red = sm + 5632;           // 2048
    float* qp  = sm + 7680;           // 1024
    float* Wrs = sm + 8704;           // 3870
    int t = threadIdx.x, lane = t & 31, w = t >> 5;
    int i0 = blockIdx.x * 8, b = blockIdx.y;

    if (do_mlp) {
        for (int q = t; q < 1024; q += 256) ats[q] = d_att[(b * 512 + i0) * 128 + q];
        __syncthreads();
        // Wo + residual (thread -> tok=w, c=lane)
        {
            const float* wo = Wo + lm * 4096;
            float acc = 0.f;
            #pragma unroll 8
            for (int m = 0; m < 128; m++) acc += ats[w * 128 + m] * wo[m * 32 + lane];
            es[w * 32 + lane] = d_emb[(b * 512 + i0 + w) * 32 + lane] + acc + bo[lm * 32 + lane];
        }
        // LN2 (warp per token)
        {
            float x = es[w * 32 + lane];
            float s1 = x;
            #pragma unroll
            for (int o = 16; o > 0; o >>= 1) s1 += __shfl_xor_sync(0xffffffffu, s1, o);
            float mu = s1 * (1.f / 32.f);
            float dd = x - mu;
            float s2 = dd * dd;
            #pragma unroll
            for (int o = 16; o > 0; o >>= 1) s2 += __shfl_xor_sync(0xffffffffu, s2, o);
            float rs = rsqrtf(s2 * (1.f / 32.f) + 1e-5f);
            h2s[w * 32 + lane] = dd * rs * ln2g[lm * 32 + lane] + ln2b[lm * 32 + lane];
        }
        __syncthreads();
        // W1 + gelu (direct LDG)
        #pragma unroll
        for (int rep = 0; rep < 2; rep++) {
            int m = t + rep * 256;
            const float* w1 = W1 + lm * 16384;
            float wcol[32];
            #pragma unroll
            for (int cc = 0; cc < 32; cc++) wcol[cc] = w1[cc * 512 + m];
            float bb = b1[lm * 512 + m];
            #pragma unroll
            for (int tok = 0; tok < 8; tok++) {
                float s = bb;
                #pragma unroll
                for (int cc = 0; cc < 32; cc++) s += h2s[tok * 32 + cc] * wcol[cc];
                tbs[tok * 512 + m] = 0.5f * s * (1.f + erff(s * 0.70710678118654752f));
            }
        }
        __syncthreads();
        // W2: m-split partials (direct LDG)
        {
            const float* w2 = W2 + lm * 16384;
            int m0 = w * 64;
            float accw[8];
            #pragma unroll
            for (int tok = 0; tok < 8; tok++) accw[tok] = 0.f;
            for (int mm = 0; mm < 64; mm++) {
                float w2v = w2[(m0 + mm) * 32 + lane];
                #pragma unroll
                for (int tok = 0; tok < 8; tok++) accw[tok] += tbs[tok * 512 + m0 + mm] * w2v;
            }
            #pragma unroll
            for (int tok = 0; tok < 8; tok++) red[(w * 8 + tok) * 32 + lane] = accw[tok];
        }
        __syncthreads();
        {
            float s = 0.f;
            #pragma unroll
            for (int ww = 0; ww < 8; ww++) s += red[(ww * 8 + w) * 32 + lane];
            float ne = es[w * 32 + lane] + s + b2[lm * 32 + lane];
            d_emb[(b * 512 + i0 + w) * 32 + lane] = ne;
            es[w * 32 + lane] = ne;
        }
    } else {
        es[t] = d_emb[(b * 512 + i0) * 32 + t];
    }

    if (!do_qkv) return;

    // Wrel staging (only weights that would be uncoalesced via LDG)
    for (int q = t; q < 3840; q += 256) {
        int f = q >> 7, c = q & 127;
        Wrs[f * 129 + c] = Wrel[lq * 3840 + q];
    }
    __syncthreads();
    // LN1 (warp per token)
    {
        float x = es[w * 32 + lane];
        float s1 = x;
        #pragma unroll
        for (int o = 16; o > 0; o >>= 1) s1 += __shfl_xor_sync(0xffffffffu, s1, o);
        float mu = s1 * (1.f / 32.f);
        float dd = x - mu;
        float s2 = dd * dd;
        #pragma unroll
        for (int o = 16; o > 0; o >>= 1) s2 += __shfl_xor_sync(0xffffffffu, s2, o);
        float rs = rsqrtf(s2 * (1.f / 32.f) + 1e-5f);
        h2s[w * 32 + lane] = dd * rs * ln1g[lq * 32 + lane] + ln1b[lq * 32 + lane];
    }
    __syncthreads();
    // QKV matmul (direct LDG), fp16 K/V out in [bh][d][j] layout
    {
        int c = t & 127, tg = t >> 7;
        int hh = c >> 5, dd = c & 31;
        int bh = b * 4 + hh;
        float rc = rcb[(lq * 4 + hh) * 32 + dd];
        float rp = rpb[(lq * 4 + hh) * 32 + dd];
        const float* wq = Wq + lq * 4096;
        const float* wk = Wk + lq * 4096;
        const float* wv = Wv + lq * 4096;
        float accq[4], acck[4], accv[4];
        #pragma unroll
        for (int tk = 0; tk < 4; tk++) { accq[tk] = 0.f; acck[tk] = 0.f; accv[tk] = 0.f; }
        for (int cc = 0; cc < 32; cc++) {
            float a = wq[cc * 128 + c], kwe = wk[cc * 128 + c], vwe = wv[cc * 128 + c];
            #pragma unroll
            for (int tk = 0; tk < 4; tk++) {
                float hc = h2s[(tg * 4 + tk) * 32 + cc];
                accq[tk] += hc * a; acck[tk] += hc * kwe; accv[tk] += hc * vwe;
            }
        }
        #pragma unroll
        for (int tk = 0; tk < 4; tk++) {
            int tok = tg * 4 + tk;
            float q = accq[tk] * 0.17677669529663687f;
            d_qcb[(bh * 512 + i0 + tok) * 32 + dd] = q + rc;
            qp[tok * 128 + c] = q + rp;
        }
        uint2 kp, vp;
        kp.x = h2u(__floats2half2_rn(acck[0], acck[1]));
        kp.y = h2u(__floats2half2_rn(acck[2], acck[3]));
        vp.x = h2u(__floats2half2_rn(accv[0], accv[1]));
        vp.y = h2u(__floats2half2_rn(accv[2], accv[3]));
        *(uint2*)&d_kkh[(bh * 32 + dd) * 512 + i0 + tg * 4] = kp;
        *(uint2*)&d_vvh[(bh * 32 + dd) * 512 + i0 + tg * 4] = vp;
    }
    __syncthreads();
    // qrel: lane = feature, warp = token
    if (lane < 30) {
        int f = lane, tok = w;
        #pragma unroll
        for (int h2 = 0; h2 < 4; h2++) {
            float s = 0.f;
            #pragma unroll
            for (int d2 = 0; d2 < 32; d2++)
                s += Wrs[f * 129 + h2 * 32 + d2] * qp[tok * 128 + h2 * 32 + d2];
            d_qrl[((b * 512 + i0 + tok) * 4 + h2) * 32 + f] = s;
        }
    }
}

// ---------------- scatter back into [B,C,L] ----------------
__global__ void scatter_kernel(float* __restrict__ out) {
    int i = blockIdx.x, b = blockIdx.y, c = threadIdx.x;
    out[((size_t)b * 32 + c) * LSEQ + d_idxg[b][i]] = d_emb[(b * 512 + i) * 32 + c];
}

// ---------------- launch ----------------
extern "C" void kernel_launch(void* const* d_in, const int* in_sizes, int n_in,
                              void* d_out, int out_size) {
    (void)in_sizes; (void)n_in;
    const float* x_skip    = (const float*)d_in[0];
    const float* attention = (const float*)d_in[1];
    const float* ln1g = (const float*)d_in[2];
    const float* ln1b = (const float*)d_in[3];
    const float* Wq   = (const float*)d_in[4];
    const float* Wk   = (const float*)d_in[5];
    const float* Wv   = (const float*)d_in[6];
    const float* Wrel = (const float*)d_in[7];
    const float* rcb  = (const float*)d_in[8];
    const float* rpb  = (const float*)d_in[9];
    const float* Wo   = (const float*)d_in[10];
    const float* bo   = (const float*)d_in[11];
    const float* ln2g = (const float*)d_in[12];
    const float* ln2b = (const float*)d_in[13];
    const float* W1   = (const float*)d_in[14];
    const float* b1   = (const float*)d_in[15];
    const float* W2   = (const float*)d_in[16];
    const float* b2   = (const float*)d_in[17];
    float* out = (float*)d_out;

    const int ATT_SMEM   = 68608;
    const int FUSED_SMEM = 12576 * 4;             // 50304 B
    const int PRO_SMEM   = 32768 + 22528 + 1024;  // 56320 B
    cudaFuncSetAttribute(attn_kernel,     cudaFuncAttributeMaxDynamicSharedMemorySize, ATT_SMEM);
    cudaFuncSetAttribute(fused_kernel,    cudaFuncAttributeMaxDynamicSharedMemorySize, FUSED_SMEM);
    cudaFuncSetAttribute(prologue_kernel, cudaFuncAttributeMaxDynamicSharedMemorySize, PRO_SMEM);

    prologue_kernel<<<36, 1024, PRO_SMEM>>>(attention);
    sortgather_kernel<<<2, 256>>>(x_skip);
    pos_kernel<<<2048, 256>>>();

    // qkv for layer 0
    fused_kernel<<<dim3(64, 2), 256, FUSED_SMEM>>>(
        Wo, bo, ln2g, ln2b, W1, b1, W2, b2,
        ln1g, ln1b, Wq, Wk, Wv, Wrel, rcb, rpb,
        0, 0, /*do_mlp=*/0, /*do_qkv=*/1);

    for (int l = 0; l < 4; l++) {
        attn_kernel<<<dim3(32, 4, 2), 256, ATT_SMEM>>>();
        fused_kernel<<<dim3(64, 2), 256, FUSED_SMEM>>>(
            Wo, bo, ln2g, ln2b, W1, b1, W2, b2,
            ln1g, ln1b, Wq, Wk, Wv, Wrel, rcb, rpb,
            l, l + 1, /*do_mlp=*/1, /*do_qkv=*/(l < 3) ? 1 : 0);
    }

    cudaMemsetAsync(d_out, 0, (size_t)out_size * sizeof(float), 0);
    scatter_kernel<<<dim3(512, 2), 32>>>(out);
}

// round 8
// speedup vs baseline: 3.3805x; 1.0431x over previous
#include <cuda_runtime.h>
#include <cuda_fp16.h>
#include <math.h>

#define LSEQ 45000

// ---------------- device scratch (no allocs allowed) ----------------
__device__ uint4 d_posh4[1048576];          // [2][512][512] * 32B (16 halfs: 15 feats + sign)
__device__ int   d_topk[2][2][256];
__device__ int   d_idxg[2][512];
__device__ float d_emb[2*512*32];
__device__ __align__(16) __half d_kkh[2*4*32*512];   // [b*4+h][d][j] fp16
__device__ __align__(16) __half d_vvh[2*4*32*512];
__device__ float d_qcb[2*4*512*32];         // q*scale + rcb   [bh][i][d]
__device__ float d_qrl[2*512*4*32];         // [b][i][h][30 used]
__device__ float d_att[2*512*128];          // attention output pre-Wo
__device__ float d_cc[24];                  // 0..4 c1, 5..9 lz, 10..14 rate, 15..19 conc-1
__device__ int   d_pmaxbits;                // global gamma max (positive-float bits)

__device__ __forceinline__ __half2 u2h(unsigned u) { return *reinterpret_cast<__half2*>(&u); }
__device__ __forceinline__ unsigned h2u(__half2 h) { return *reinterpret_cast<unsigned*>(&h); }

// ---------------- prologue: blocks 0-3 top-256 select, blocks 4-35 basis setup ----------------
#define TK_CAP 2816
__global__ void __launch_bounds__(1024) prologue_kernel(const float* __restrict__ att) {
    extern __shared__ unsigned char tks[];
    int t = threadIdx.x, lane = t & 31;

    if (blockIdx.x >= 4) {
        float* red = (float*)tks;
        int bid = blockIdx.x - 4;
        double L2S = log(45000.0) / log(2.0);
        float c1[5], lz[5], rate[5], cm1[5];
        for (int k = 0; k < 5; k++) {
            double lin = 3.0 + (L2S - 3.0) * ((double)k / 4.0);
            float hl = (float)exp2(lin);
            c1[k] = -0.69314718055994531f / hl;
            double mean = 9000.0 * (k + 1);
            double sd = 4500.0;
            float conc = (float)((mean / sd) * (mean / sd));
            float rt = (float)(mean / (sd * sd));
            rate[k] = rt; cm1[k] = conc - 1.0f;
            lz[k] = lgammaf(conc) - conc * logf(rt);
        }
        float m = 1e-8f;
        for (int a_ = bid * 1024 + t; a_ < LSEQ; a_ += 32768) {
            if (a_ == 0) continue;
            float a = (float)a_;
            float la = logf(a);
            for (int k = 0; k < 5; k++) {
                float p = expf(cm1[k] * la - rate[k] * a - lz[k]) + 1e-8f;
                m = fmaxf(m, p);
            }
        }
        red[t] = m; __syncthreads();
        for (int s = 512; s > 0; s >>= 1) {
            if (t < s) red[t] = fmaxf(red[t], red[t + s]);
            __syncthreads();
        }
        if (t == 0) atomicMax(&d_pmaxbits, __float_as_int(red[0]));
        if (bid == 0 && t == 0) {
            for (int k = 0; k < 5; k++) { d_cc[k] = c1[k]; d_cc[5+k] = lz[k]; d_cc[10+k] = rate[k]; d_cc[15+k] = cm1[k]; }
        }
        return;
    }

    unsigned* hist = (unsigned*)tks;                                     // 8192 u
    unsigned long long* cand = (unsigned long long*)(tks + 32768);       // 2816
    unsigned* ps = (unsigned*)(tks + 32768 + 22528);                     // 256
    __shared__ unsigned thrT;
    __shared__ int cnt, ocnt, rem_s;
    __shared__ unsigned long long pref_s;
    int b = blockIdx.x >> 1, ch = (blockIdx.x & 1) + 1;
    const float* vals = att + (size_t)(b * 3 + ch) * LSEQ;
    for (int i = t; i < 8192; i += 1024) hist[i] = 0;
    if (t == 0) { cnt = 0; ocnt = 0; pref_s = 0ull; rem_s = 256; }
    __syncthreads();
    for (int j = t; j < LSEQ; j += 1024) {
        unsigned u = __float_as_uint(vals[j]);
        u = (u & 0x80000000u) ? ~u : (u | 0x80000000u);
        atomicAdd(&hist[u >> 19], 1u);
    }
    __syncthreads();
    if (t < 256) {
        unsigned sum = 0;
        int base = 8191 - t * 32;
        for (int k = 0; k < 32; k++) sum += hist[base - k];
        ps[t] = sum;
    }
    __syncthreads();
    if (t < 32) {
        unsigned s = 0;
        #pragma unroll
        for (int k = 0; k < 8; k++) s += ps[lane * 8 + k];
        unsigned pre = s;
        #pragma unroll
        for (int o = 1; o < 32; o <<= 1) { unsigned v = __shfl_up_sync(0xffffffffu, pre, o); if (lane >= o) pre += v; }
        bool hit = (pre >= 256u) && (pre - s) < 256u;
        unsigned mk = __ballot_sync(0xffffffffu, hit);
        if (lane == (__ffs(mk) - 1)) {
            unsigned cum = pre - s;
            int T = 0;
            for (int k = 0; k < 8; k++) {
                int ci = lane * 8 + k;
                if (cum + ps[ci] >= 256u) {
                    int base = 8191 - ci * 32;
                    for (int kk = 0; kk < 32; kk++) { cum += hist[base - kk]; if (cum >= 256u) { T = base - kk; break; } }
                    break;
                }
                cum += ps[ci];
            }
            thrT = (unsigned)T;
        }
    }
    __syncthreads();
    unsigned T = thrT;
    for (int j = t; j < LSEQ; j += 1024) {
        unsigned u = __float_as_uint(vals[j]);
        u = (u & 0x80000000u) ? ~u : (u | 0x80000000u);
        if ((u >> 19) >= T) {
            int pi = atomicAdd(&cnt, 1);
            if (pi < TK_CAP) cand[pi] = (((unsigned long long)u) << 32) | (unsigned)(0xFFFFFFFFu - (unsigned)j);
        }
    }
    __syncthreads();
    int n = cnt < TK_CAP ? cnt : TK_CAP;
    for (int shift = 56; shift >= 0; shift -= 8) {
        if (t < 256) hist[t] = 0;
        __syncthreads();
        unsigned long long p = pref_s;
        unsigned long long mh = (shift == 56) ? 0ull : ~((1ull << (shift + 8)) - 1ull);
        for (int i = t; i < n; i += 1024) {
            unsigned long long k = cand[i];
            if ((k & mh) == p) atomicAdd(&hist[(unsigned)(k >> shift) & 255u], 1u);
        }
        __syncthreads();
        if (t < 32) {
            int r = rem_s;
            unsigned s = 0;
            #pragma unroll
            for (int k = 0; k < 8; k++) s += hist[255 - (lane * 8 + k)];
            unsigned pre = s;
            #pragma unroll
            for (int o = 1; o < 32; o <<= 1) { unsigned v = __shfl_up_sync(0xffffffffu, pre, o); if (lane >= o) pre += v; }
            bool hit = ((int)pre >= r) && (int)(pre - s) < r;
            unsigned mk = __ballot_sync(0xffffffffu, hit);
            if (lane == (__ffs(mk) - 1)) {
                unsigned cum = pre - s;
                for (int k = 0; k < 8; k++) {
                    int bin = 255 - (lane * 8 + k);
                    cum += hist[bin];
                    if ((int)cum >= r) { rem_s = r - (int)(cum - hist[bin]); pref_s = p | ((unsigned long long)bin << shift); break; }
                }
            }
        }
        __syncthreads();
    }
    unsigned long long kth = pref_s;
    for (int i = t; i < n; i += 1024) {
        if (cand[i] >= kth) {
            int pi = atomicAdd(&ocnt, 1);
            if (pi < 256) d_topk[b][ch - 1][pi] = (int)(0xFFFFFFFFu - (unsigned)(cand[i] & 0xFFFFFFFFull));
        }
    }
}

// ---------------- merge+sort 512 indices, gather embeddings ----------------
__global__ void __launch_bounds__(256) sortgather_kernel(const float* __restrict__ x_skip) {
    int b = blockIdx.x, t = threadIdx.x;
    __shared__ int s[512];
    s[t] = d_topk[b][0][t];
    s[256 + t] = d_topk[b][1][t];
    __syncthreads();
    for (int k = 2; k <= 512; k <<= 1) {
        for (int j = k >> 1; j > 0; j >>= 1) {
            #pragma unroll
            for (int half = 0; half < 2; half++) {
                int idx = half * 256 + t;
                int ixj = idx ^ j;
                if (ixj > idx) {
                    int a = s[idx], c = s[ixj];
                    bool up = ((idx & k) == 0);
                    if ((a > c) == up) { s[idx] = c; s[ixj] = a; }
                }
            }
            __syncthreads();
        }
    }
    d_idxg[b][t] = s[t];
    d_idxg[b][256 + t] = s[256 + t];
    __syncthreads();
    for (int q = t; q < 512 * 32; q += 256) {
        int i = q >> 5, c = q & 31;
        d_emb[(b * 512 + i) * 32 + c] = x_skip[((size_t)b * 32 + c) * LSEQ + s[i]];
    }
}

// ---------------- positional basis features (layer-invariant, fp16 packed) ----------------
__global__ void __launch_bounds__(256) pos_kernel() {
    unsigned int id = blockIdx.x * 256u + threadIdx.x;   // 2*512*512 threads
    int b = id >> 18;
    unsigned int r = id & 262143u;
    int i = r >> 9, j = r & 511;
    int d = d_idxg[b][i] - d_idxg[b][j];
    float a = fabsf((float)d);
    float sg = (d > 0) ? 1.f : ((d < 0) ? -1.f : 0.f);
    float f[16];
    #pragma unroll
    for (int k = 0; k < 5; k++) f[k] = expf(d_cc[k] * a);
    f[5] = (1.f  > a) ? 1.f : 0.f;
    f[6] = (3.f  > a) ? 1.f : 0.f;
    f[7] = (7.f  > a) ? 1.f : 0.f;
    f[8] = (15.f > a) ? 1.f : 0.f;
    f[9] = (31.f > a) ? 1.f : 0.f;
    float la = logf(a);                 // a==0 -> -inf -> exp -> 0 (matches xlogy path)
    float invp = 1.0f / __int_as_float(d_pmaxbits);
    #pragma unroll
    for (int k = 0; k < 5; k++) {
        float lp = d_cc[15 + k] * la - d_cc[10 + k] * a;
        f[10 + k] = (expf(lp - d_cc[5 + k]) + 1e-8f) * invp;
    }
    f[15] = sg;
    unsigned u[8];
    #pragma unroll
    for (int k = 0; k < 8; k++) u[k] = h2u(__floats2half2_rn(f[2 * k], f[2 * k + 1]));
    uint4* o = d_posh4 + (size_t)id * 2u;
    o[0] = make_uint4(u[0], u[1], u[2], u[3]);
    o[1] = make_uint4(u[4], u[5], u[6], u[7]);
}

// ---------------- attention: 16 rows/block, 2 rows/warp, fp16 K/V [d][j], 2 CTA/SM ----------------
__global__ void __launch_bounds__(256, 2) attn_kernel() {
    extern __shared__ __align__(16) unsigned char smraw[];
    __half* Kh = (__half*)smraw;                       // 32KB
    __half* Vh = (__half*)(smraw + 32768);             // 32KB
    float* qcs = (float*)(smraw + 65536);              // 512 f
    unsigned* qAh = (unsigned*)(smraw + 67584);        // 128 u
    unsigned* qBh = (unsigned*)(smraw + 68096);        // 128 u
    int t = threadIdx.x, lane = t & 31, w = t >> 5;
    int i0 = blockIdx.x * 16;
    int hd = blockIdx.y;
    int b = blockIdx.z;
    int bh = b * 4 + hd;

    {
        const uint4* kg = (const uint4*)(d_kkh + bh * 16384);
        const uint4* vg = (const uint4*)(d_vvh + bh * 16384);
        uint4* ks4 = (uint4*)Kh; uint4* vs4 = (uint4*)Vh;
        for (int q = t; q < 2048; q += 256) { ks4[q] = kg[q]; vs4[q] = vg[q]; }
    }
    for (int q = t; q < 512; q += 256)
        qcs[q] = d_qcb[(bh * 512 + i0 + (q >> 5)) * 32 + (q & 31)];
    if (t < 128) {
        int r = t >> 3, p = t & 7;
        const float* qr = d_qrl + (((b * 512) + i0 + r) * 4 + hd) * 32;
        int f0 = 2 * p, f1 = f0 + 1;
        float a0 = qr[f0],      a1 = (f1 < 15) ? qr[f1] : 0.f;
        float b0 = qr[15 + f0], b1 = (f1 < 15) ? qr[15 + f1] : 0.f;
        qAh[r * 8 + p] = h2u(__floats2half2_rn(a0, a1));
        qBh[r * 8 + p] = h2u(__floats2half2_rn(b0, b1));
    }
    __syncthreads();

    int r0 = 2 * w, r1 = r0 + 1;
    float s0[16], s1[16];
    #pragma unroll
    for (int q = 0; q < 16; q++) { s0[q] = 0.f; s1[q] = 0.f; }

    for (int d = 0; d < 32; d++) {
        float qv0 = qcs[r0 * 32 + d], qv1 = qcs[r1 * 32 + d];
        const uint2* kr = (const uint2*)(Kh + d * 512);
        #pragma unroll
        for (int ch = 0; ch < 4; ch++) {
            uint2 kk = kr[ch * 32 + lane];
            float2 fa = __half22float2(u2h(kk.x));
            float2 fb = __half22float2(u2h(kk.y));
            s0[ch*4+0] += qv0 * fa.x; s0[ch*4+1] += qv0 * fa.y;
            s0[ch*4+2] += qv0 * fb.x; s0[ch*4+3] += qv0 * fb.y;
            s1[ch*4+0] += qv1 * fa.x; s1[ch*4+1] += qv1 * fa.y;
            s1[ch*4+2] += qv1 * fb.x; s1[ch*4+3] += qv1 * fb.y;
        }
    }

    {
        __half2 qa0[8], qb0[8], qa1[8], qb1[8];
        #pragma unroll
        for (int p = 0; p < 8; p++) {
            qa0[p] = u2h(qAh[r0 * 8 + p]); qb0[p] = u2h(qBh[r0 * 8 + p]);
            qa1[p] = u2h(qAh[r1 * 8 + p]); qb1[p] = u2h(qBh[r1 * 8 + p]);
        }
        const uint4* prow0 = d_posh4 + 2 * (size_t)((b * 512 + i0 + r0) * 512);
        const uint4* prow1 = d_posh4 + 2 * (size_t)((b * 512 + i0 + r1) * 512);
        #pragma unroll
        for (int ch = 0; ch < 4; ch++) {
            #pragma unroll
            for (int u = 0; u < 4; u++) {
                int j = ch * 128 + lane * 4 + u;
                {
                    uint4 A = prow0[2 * j], B = prow0[2 * j + 1];
                    __half2 sA = __hmul2(u2h(A.x), qa0[0]);
                    sA = __hfma2(u2h(A.y), qa0[1], sA); sA = __hfma2(u2h(A.z), qa0[2], sA);
                    sA = __hfma2(u2h(A.w), qa0[3], sA); sA = __hfma2(u2h(B.x), qa0[4], sA);
                    sA = __hfma2(u2h(B.y), qa0[5], sA); sA = __hfma2(u2h(B.z), qa0[6], sA);
                    sA = __hfma2(u2h(B.w), qa0[7], sA);
                    __half2 sB = __hmul2(u2h(A.x), qb0[0]);
                    sB = __hfma2(u2h(A.y), qb0[1], sB); sB = __hfma2(u2h(A.z), qb0[2], sB);
                    sB = __hfma2(u2h(A.w), qb0[3], sB); sB = __hfma2(u2h(B.x), qb0[4], sB);
                    sB = __hfma2(u2h(B.y), qb0[5], sB); sB = __hfma2(u2h(B.z), qb0[6], sB);
                    sB = __hfma2(u2h(B.w), qb0[7], sB);
                    float2 fA = __half22float2(sA), fB = __half22float2(sB);
                    float sg = __high2float(u2h(B.w));
                    s0[ch * 4 + u] += (fA.x + fA.y) + sg * (fB.x + fB.y);
                }
                {
                    uint4 A = prow1[2 * j], B = prow1[2 * j + 1];
                    __half2 sA = __hmul2(u2h(A.x), qa1[0]);
                    sA = __hfma2(u2h(A.y), qa1[1], sA); sA = __hfma2(u2h(A.z), qa1[2], sA);
                    sA = __hfma2(u2h(A.w), qa1[3], sA); sA = __hfma2(u2h(B.x), qa1[4], sA);
                    sA = __hfma2(u2h(B.y), qa1[5], sA); sA = __hfma2(u2h(B.z), qa1[6], sA);
                    sA = __hfma2(u2h(B.w), qa1[7], sA);
                    __half2 sB = __hmul2(u2h(A.x), qb1[0]);
                    sB = __hfma2(u2h(A.y), qb1[1], sB); sB = __hfma2(u2h(A.z), qb1[2], sB);
                    sB = __hfma2(u2h(A.w), qb1[3], sB); sB = __hfma2(u2h(B.x), qb1[4], sB);
                    sB = __hfma2(u2h(B.y), qb1[5], sB); sB = __hfma2(u2h(B.z), qb1[6], sB);
                    sB = __hfma2(u2h(B.w), qb1[7], sB);
                    float2 fA = __half22float2(sA), fB = __half22float2(sB);
                    float sg = __high2float(u2h(B.w));
                    s1[ch * 4 + u] += (fA.x + fA.y) + sg * (fB.x + fB.y);
                }
            }
        }
    }

    float m0 = -3.0e38f, m1 = -3.0e38f;
    #pragma unroll
    for (int q = 0; q < 16; q++) { m0 = fmaxf(m0, s0[q]); m1 = fmaxf(m1, s1[q]); }
    #pragma unroll
    for (int o = 16; o > 0; o >>= 1) {
        m0 = fmaxf(m0, __shfl_xor_sync(0xffffffffu, m0, o));
        m1 = fmaxf(m1, __shfl_xor_sync(0xffffffffu, m1, o));
    }
    float su0 = 0.f, su1 = 0.f;
    #pragma unroll
    for (int q = 0; q < 16; q++) {
        s0[q] = expf(s0[q] - m0); su0 += s0[q];
        s1[q] = expf(s1[q] - m1); su1 += s1[q];
    }
    #pragma unroll
    for (int o = 16; o > 0; o >>= 1) {
        su0 += __shfl_xor_sync(0xffffffffu, su0, o);
        su1 += __shfl_xor_sync(0xffffffffu, su1, o);
    }
    float inv0 = 1.f / su0, inv1 = 1.f / su1;

    #pragma unroll
    for (int pass = 0; pass < 2; pass++) {
        float v[32];
        #pragma unroll
        for (int k = 0; k < 16; k++) {
            int d = pass * 16 + k;
            const uint2* vr = (const uint2*)(Vh + d * 512);
            float a0 = 0.f, a1 = 0.f;
            #pragma unroll
            for (int ch = 0; ch < 4; ch++) {
                uint2 vv = vr[ch * 32 + lane];
                float2 fa = __half22float2(u2h(vv.x));
                float2 fb = __half22float2(u2h(vv.y));
                a0 += s0[ch*4+0]*fa.x + s0[ch*4+1]*fa.y + s0[ch*4+2]*fb.x + s0[ch*4+3]*fb.y;
                a1 += s1[ch*4+0]*fa.x + s1[ch*4+1]*fa.y + s1[ch*4+2]*fb.x + s1[ch*4+3]*fb.y;
            }
            v[k] = a0; v[16 + k] = a1;
        }
        #pragma unroll
        for (int m = 16; m >= 1; m >>= 1) {
            #pragma unroll
            for (int k = 0; k < m; k++) {
                float give = (lane & m) ? v[k] : v[k + m];
                float got = __shfl_xor_sync(0xffffffffu, give, m);
                v[k] = (lane & m) ? (v[k + m] + got) : (v[k] + got);
            }
        }
        float outv = v[0] * ((lane < 16) ? inv0 : inv1);
        int row = (lane < 16) ? r0 : r1;
        int dd = (lane & 15) + pass * 16;
        d_att[(b * 512 + i0 + row) * 128 + hd * 32 + dd] = outv;
    }
}

// ---------------- fused: [mlp lm] + [qkv lq], 8 tokens/block, 512 threads ----------------
__global__ void __launch_bounds__(512, 1) fused_kernel(
    const float* __restrict__ Wo, const float* __restrict__ bo,
    const float* __restrict__ ln2g, const float* __restrict__ ln2b,
    const float* __restrict__ W1, const float* __restrict__ b1,
    const float* __restrict__ W2, const float* __restrict__ b2,
    const float* __restrict__ ln1g, const float* __restrict__ ln1b,
    const float* __restrict__ Wq, const float* __restrict__ Wk, const float* __restrict__ Wv,
    const float* __restrict__ Wrel, const float* __restrict__ rcb, const float* __restrict__ rpb,
    int lm, int lq, int do_mlp, int do_qkv)
{
    extern __shared__ float sm[];
    float* ats = sm;                  // 1024
    float* es  = sm + 1024;           // 256
    float* h2s = sm + 1280;           // 256
    float* tbs = sm + 1536;           // 4096
    float* red = sm + 5632;           // 4096
    float* qp  = sm + 9728;           // 1024
    float* Wrs = sm + 10752;          // 3870 -> 14622 floats total
    int t = threadIdx.x, lane = t & 31, w = t >> 5;
    int i0 = blockIdx.x * 8, b = blockIdx.y;

    // hoist Wrel staging so its LDGs overlap everything below
    if (do_qkv) {
        for (int q = t; q < 3840; q += 512) {
            int f = q >> 7, c = q & 127;
            Wrs[f * 129 + c] = Wrel[lq * 3840 + q];
        }
    }

    if (do_mlp) {
        for (int q = t; q < 1024; q += 512) ats[q] = d_att[(b * 512 + i0) * 128 + q];
        __syncthreads();
        // Wo + residual: 2-way m-split per output, lane-pair combine
        {
            int oi = t >> 1, hf = t & 1;
            int tok = oi >> 5, c = oi & 31;
            const float* wo = Wo + lm * 4096;
            int mb = hf * 64;
            float acc = 0.f;
            #pragma unroll 16
            for (int m = 0; m < 64; m++) acc += ats[tok * 128 + mb + m] * wo[(mb + m) * 32 + c];
            acc += __shfl_xor_sync(0xffffffffu, acc, 1);
            if (hf == 0) es[oi] = d_emb[(b * 512 + i0 + tok) * 32 + c] + acc + bo[lm * 32 + c];
        }
        __syncthreads();
        // LN2 (warps 0..7, one token each)
        if (w < 8) {
            float x = es[w * 32 + lane];
            float s1 = x;
            #pragma unroll
            for (int o = 16; o > 0; o >>= 1) s1 += __shfl_xor_sync(0xffffffffu, s1, o);
            float mu = s1 * (1.f / 32.f);
            float dd = x - mu;
            float s2 = dd * dd;
            #pragma unroll
            for (int o = 16; o > 0; o >>= 1) s2 += __shfl_xor_sync(0xffffffffu, s2, o);
            float rs = rsqrtf(s2 * (1.f / 32.f) + 1e-5f);
            h2s[w * 32 + lane] = dd * rs * ln2g[lm * 32 + lane] + ln2b[lm * 32 + lane];
        }
        __syncthreads();
        // W1 + gelu: thread t owns column m=t
        {
            int m = t;
            const float* w1 = W1 + lm * 16384;
            float wcol[32];
            #pragma unroll
            for (int cc = 0; cc < 32; cc++) wcol[cc] = w1[cc * 512 + m];
            float bb = b1[lm * 512 + m];
            #pragma unroll
            for (int tok = 0; tok < 8; tok++) {
                float s = bb;
                #pragma unroll
                for (int cc = 0; cc < 32; cc++) s += h2s[tok * 32 + cc] * wcol[cc];
                tbs[tok * 512 + m] = 0.5f * s * (1.f + erff(s * 0.70710678118654752f));
            }
        }
        __syncthreads();
        // W2: 16 warps x 32 rows m-split
        {
            const float* w2 = W2 + lm * 16384;
            int m0 = w * 32;
            float accw[8];
            #pragma unroll
            for (int tok = 0; tok < 8; tok++) accw[tok] = 0.f;
            #pragma unroll 4
            for (int mm = 0; mm < 32; mm++) {
                float w2v = w2[(m0 + mm) * 32 + lane];
                #pragma unroll
                for (int tok = 0; tok < 8; tok++) accw[tok] += tbs[tok * 512 + m0 + mm] * w2v;
            }
            #pragma unroll
            for (int tok = 0; tok < 8; tok++) red[(w * 8 + tok) * 32 + lane] = accw[tok];
        }
        __syncthreads();
        if (t < 256) {
            int tok = t >> 5, c = t & 31;
            float s = 0.f;
            #pragma unroll
            for (int ww = 0; ww < 16; ww++) s += red[(ww * 8 + tok) * 32 + c];
            float ne = es[t] + s + b2[lm * 32 + c];
            d_emb[(b * 512 + i0 + tok) * 32 + c] = ne;
            es[t] = ne;
        }
    } else {
        if (t < 256) es[t] = d_emb[(b * 512 + i0) * 32 + t];
    }
    __syncthreads();

    if (!do_qkv) return;

    // LN1 (warps 0..7)
    if (w < 8) {
        float x = es[w * 32 + lane];
        float s1 = x;
        #pragma unroll
        for (int o = 16; o > 0; o >>= 1) s1 += __shfl_xor_sync(0xffffffffu, s1, o);
        float mu = s1 * (1.f / 32.f);
        float dd = x - mu;
        float s2 = dd * dd;
        #pragma unroll
        for (int o = 16; o > 0; o >>= 1) s2 += __shfl_xor_sync(0xffffffffu, s2, o);
        float rs = rsqrtf(s2 * (1.f / 32.f) + 1e-5f);
        h2s[w * 32 + lane] = dd * rs * ln1g[lq * 32 + lane] + ln1b[lq * 32 + lane];
    }
    __syncthreads();
    // QKV: c = t&127, tg = t>>7 in {0..3}, 2 tokens each
    {
        int c = t & 127, tg = t >> 7;
        int hh = c >> 5, dd = c & 31;
        int bh = b * 4 + hh;
        float rc = rcb[(lq * 4 + hh) * 32 + dd];
        float rp = rpb[(lq * 4 + hh) * 32 + dd];
        const float* wq = Wq + lq * 4096;
        const float* wk = Wk + lq * 4096;
        const float* wv = Wv + lq * 4096;
        float accq[2] = {0.f, 0.f}, acck[2] = {0.f, 0.f}, accv[2] = {0.f, 0.f};
        #pragma unroll 8
        for (int cc = 0; cc < 32; cc++) {
            float a = wq[cc * 128 + c], kwe = wk[cc * 128 + c], vwe = wv[cc * 128 + c];
            #pragma unroll
            for (int tk = 0; tk < 2; tk++) {
                float hc = h2s[(tg * 2 + tk) * 32 + cc];
                accq[tk] += hc * a; acck[tk] += hc * kwe; accv[tk] += hc * vwe;
            }
        }
        #pragma unroll
        for (int tk = 0; tk < 2; tk++) {
            int tok = tg * 2 + tk;
            float q = accq[tk] * 0.17677669529663687f;
            d_qcb[(bh * 512 + i0 + tok) * 32 + dd] = q + rc;
            qp[tok * 128 + c] = q + rp;
        }
        *(unsigned*)&d_kkh[(bh * 32 + dd) * 512 + i0 + tg * 2] = h2u(__floats2half2_rn(acck[0], acck[1]));
        *(unsigned*)&d_vvh[(bh * 32 + dd) * 512 + i0 + tg * 2] = h2u(__floats2half2_rn(accv[0], accv[1]));
    }
    __syncthreads();
    // qrel: warp w -> token w>>1, heads (w&1)*2 .. +1
    if (lane < 30) {
        int f = lane, tok = w >> 1, h2b = (w & 1) * 2;
        #pragma unroll
        for (int k = 0; k < 2; k++) {
            int hh2 = h2b + k;
            float s = 0.f;
            #pragma unroll
            for (int d2 = 0; d2 < 32; d2++)
                s += Wrs[f * 129 + hh2 * 32 + d2] * qp[tok * 128 + hh2 * 32 + d2];
            d_qrl[((b * 512 + i0 + tok) * 4 + hh2) * 32 + f] = s;
        }
    }
}

// ---------------- scatter back into [B,C,L] ----------------
__global__ void scatter_kernel(float* __restrict__ out) {
    int i = blockIdx.x, b = blockIdx.y, c = threadIdx.x;
    out[((size_t)b * 32 + c) * LSEQ + d_idxg[b][i]] = d_emb[(b * 512 + i) * 32 + c];
}

// ---------------- launch ----------------
extern "C" void kernel_launch(void* const* d_in, const int* in_sizes, int n_in,
                              void* d_out, int out_size) {
    (void)in_sizes; (void)n_in;
    const float* x_skip    = (const float*)d_in[0];
    const float* attention = (const float*)d_in[1];
    const float* ln1g = (const float*)d_in[2];
    const float* ln1b = (const float*)d_in[3];
    const float* Wq   = (const float*)d_in[4];
    const float* Wk   = (const float*)d_in[5];
    const float* Wv   = (const float*)d_in[6];
    const float* Wrel = (const float*)d_in[7];
    const float* rcb  = (const float*)d_in[8];
    const float* rpb  = (const float*)d_in[9];
    const float* Wo   = (const float*)d_in[10];
    const float* bo   = (const float*)d_in[11];
    const float* ln2g = (const float*)d_in[12];
    const float* ln2b = (const float*)d_in[13];
    const float* W1   = (const float*)d_in[14];
    const float* b1   = (const float*)d_in[15];
    const float* W2   = (const float*)d_in[16];
    const float* b2   = (const float*)d_in[17];
    float* out = (float*)d_out;

    const int ATT_SMEM   = 68608;
    const int FUSED_SMEM = 14622 * 4;             // 58488 B
    const int PRO_SMEM   = 32768 + 22528 + 1024;  // 56320 B
    cudaFuncSetAttribute(attn_kernel,     cudaFuncAttributeMaxDynamicSharedMemorySize, ATT_SMEM);
    cudaFuncSetAttribute(fused_kernel,    cudaFuncAttributeMaxDynamicSharedMemorySize, FUSED_SMEM);
    cudaFuncSetAttribute(prologue_kernel, cudaFuncAttributeMaxDynamicSharedMemorySize, PRO_SMEM);

    cudaMemsetAsync(d_out, 0, (size_t)out_size * sizeof(float), 0);
    prologue_kernel<<<36, 1024, PRO_SMEM>>>(attention);
    sortgather_kernel<<<2, 256>>>(x_skip);
    pos_kernel<<<2048, 256>>>();

    // qkv for layer 0
    fused_kernel<<<dim3(64, 2), 512, FUSED_SMEM>>>(
        Wo, bo, ln2g, ln2b, W1, b1, W2, b2,
        ln1g, ln1b, Wq, Wk, Wv, Wrel, rcb, rpb,
        0, 0, /*do_mlp=*/0, /*do_qkv=*/1);

    for (int l = 0; l < 4; l++) {
        attn_kernel<<<dim3(32, 4, 2), 256, ATT_SMEM>>>();
        fused_kernel<<<dim3(64, 2), 512, FUSED_SMEM>>>(
            Wo, bo, ln2g, ln2b, W1, b1, W2, b2,
            ln1g, ln1b, Wq, Wk, Wv, Wrel, rcb, rpb,
            l, l + 1, /*do_mlp=*/1, /*do_qkv=*/(l < 3) ? 1 : 0);
    }

    scatter_kernel<<<dim3(512, 2), 32>>>(out);
}